// round 7
// baseline (speedup 1.0000x reference)
#include <cuda_runtime.h>
#include <cuda_bf16.h>
#include <math.h>
#include <stdint.h>

// Problem constants (shapes fixed by the dataset)
#define NN 100000           // nodes
#define NE 1000000          // edges
#define ET 4                // edge types
#define DI 64               // input dim
#define DH 256              // hidden dim
#define KU (ET*DI)          // 256 = update row width
#define G3 (3*DI)           // 192 = gate width

// Scratch (device globals — allocation-free)
__device__ float g_update[(size_t)NN * KU];   // 102.4 MB
__device__ float g_hidden[(size_t)NN * DH];   // 102.4 MB
__device__ float g_gh[(size_t)NN * G3];       // 76.8 MB
__device__ int   g_src[NE];
__device__ int   g_dst[NE];
__device__ int   g_typ[NE];
__device__ int   g_is_i32;                    // 1 => edge arrays are int32

// ---------------------------------------------------------------------------
// Index-dtype probe (unchanged — known good)
// ---------------------------------------------------------------------------
__global__ void flag_reset_kernel() { g_is_i32 = 0; }

__global__ void probe_kernel(const long long* __restrict__ eidx) {
    int i = blockIdx.x * blockDim.x + threadIdx.x;   // 4096 probes
    long long v = eidx[i];
    if (v < 0 || v >= (long long)NN) atomicExch(&g_is_i32, 1);
}

__global__ void convert_kernel(const void* __restrict__ eidx,
                               const void* __restrict__ etype) {
    int e = blockIdx.x * blockDim.x + threadIdx.x;
    if (e >= NE) return;
    if (g_is_i32) {
        const int* p = (const int*)eidx;
        g_src[e] = p[e];
        g_dst[e] = p[NE + e];
        g_typ[e] = ((const int*)etype)[e];
    } else {
        const long long* p = (const long long*)eidx;
        g_src[e] = (int)p[e];
        g_dst[e] = (int)p[NE + e];
        g_typ[e] = (int)((const long long*)etype)[e];
    }
}

// ---------------------------------------------------------------------------
// Zero the update accumulator
// ---------------------------------------------------------------------------
__global__ void zero_kernel(float4* __restrict__ p, int n4) {
    int i = blockIdx.x * blockDim.x + threadIdx.x;
    if (i < n4) p[i] = make_float4(0.f, 0.f, 0.f, 0.f);
}

// ---------------------------------------------------------------------------
// Edge scatter with vectorized L2 reduction (red.global.add.v4.f32).
// ---------------------------------------------------------------------------
__global__ void scatter_kernel(const float* __restrict__ x,
                               const float* __restrict__ ew,
                               float* __restrict__ upd) {
    int i = blockIdx.x * blockDim.x + threadIdx.x;   // NE*16 work items
    int e = i >> 4;
    int c = i & 15;
    if (e >= NE) return;
    int src = g_src[e];
    int dst = g_dst[e];
    int t   = g_typ[e];
    if ((unsigned)src >= NN || (unsigned)dst >= NN || (unsigned)t >= ET) return;
    float w = ew[e];
    float4 v = *(const float4*)(x + (size_t)src * DI + c * 4);
    float* drow = upd + ((size_t)dst * ET + t) * DI + c * 4;
    asm volatile("red.global.add.v4.f32 [%0], {%1,%2,%3,%4};"
                 :: "l"(drow), "f"(w * v.x), "f"(w * v.y),
                    "f"(w * v.z), "f"(w * v.w)
                 : "memory");
}

// ---------------------------------------------------------------------------
// TF32 mma helpers
// ---------------------------------------------------------------------------
#define MMA_TF32(d, a, b0, b1)                                                 \
    asm volatile(                                                              \
        "mma.sync.aligned.m16n8k8.row.col.f32.tf32.tf32.f32 "                  \
        "{%0,%1,%2,%3},{%4,%5,%6,%7},{%8,%9},{%0,%1,%2,%3};"                   \
        : "+f"((d)[0]), "+f"((d)[1]), "+f"((d)[2]), "+f"((d)[3])               \
        : "r"((a)[0]), "r"((a)[1]), "r"((a)[2]), "r"((a)[3]),                  \
          "r"(b0), "r"(b1))

__device__ __forceinline__ uint32_t to_tf32(float v) {
    uint32_t u;
    asm("cvt.rna.tf32.f32 %0, %1;" : "=r"(u) : "f"(v));
    return u;
}

__device__ __forceinline__ float sigmoidf_(float v) {
    return 1.f / (1.f + expf(-v));
}

// ---------------------------------------------------------------------------
// TF32 GEMM: C[M,N] = epi(A[M,K] @ B[N,K]^T + bias[N])
// Block 128x64, 8 warps (4x2), warp tile 32x32, BK=16.
// Grid: x = N-blocks, y = M-blocks  (consecutive CTAs share the A tile in L2).
// ---------------------------------------------------------------------------
template<int K, int RELU>
__global__ void __launch_bounds__(256) gemm_tf32(const float* __restrict__ A,
                                                 const float* __restrict__ B,
                                                 const float* __restrict__ bias,
                                                 float* __restrict__ C,
                                                 int M, int N) {
    __shared__ uint32_t As[128][20];
    __shared__ uint32_t Bs[64][20];

    const int tid  = threadIdx.x;
    const int lane = tid & 31;
    const int w    = tid >> 5;
    const int wm   = (w & 3) * 32;
    const int wn   = (w >> 2) * 32;
    const int m0   = blockIdx.y * 128;
    const int n0   = blockIdx.x * 64;

    const int lrow = tid >> 2;
    const int lcol = (tid & 3) * 4;

    float acc[2][4][4];
#pragma unroll
    for (int mt = 0; mt < 2; mt++)
#pragma unroll
        for (int nt = 0; nt < 4; nt++)
#pragma unroll
            for (int j = 0; j < 4; j++) acc[mt][nt][j] = 0.f;

    for (int k0 = 0; k0 < K; k0 += 16) {
#pragma unroll
        for (int p = 0; p < 2; p++) {
            int r  = p * 64 + lrow;
            int gm = m0 + r;
            float4 v = make_float4(0.f, 0.f, 0.f, 0.f);
            if (gm < M) v = *(const float4*)(A + (size_t)gm * K + k0 + lcol);
            As[r][lcol + 0] = to_tf32(v.x);
            As[r][lcol + 1] = to_tf32(v.y);
            As[r][lcol + 2] = to_tf32(v.z);
            As[r][lcol + 3] = to_tf32(v.w);
        }
        {
            float4 v = *(const float4*)(B + (size_t)(n0 + lrow) * K + k0 + lcol);
            Bs[lrow][lcol + 0] = to_tf32(v.x);
            Bs[lrow][lcol + 1] = to_tf32(v.y);
            Bs[lrow][lcol + 2] = to_tf32(v.z);
            Bs[lrow][lcol + 3] = to_tf32(v.w);
        }
        __syncthreads();

#pragma unroll
        for (int ks = 0; ks < 16; ks += 8) {
            uint32_t af[2][4];
#pragma unroll
            for (int mt = 0; mt < 2; mt++) {
                int r = wm + mt * 16 + (lane >> 2);
                int c = ks + (lane & 3);
                af[mt][0] = As[r][c];
                af[mt][1] = As[r + 8][c];
                af[mt][2] = As[r][c + 4];
                af[mt][3] = As[r + 8][c + 4];
            }
#pragma unroll
            for (int nt = 0; nt < 4; nt++) {
                int cn = wn + nt * 8 + (lane >> 2);
                int ck = ks + (lane & 3);
                uint32_t b0 = Bs[cn][ck];
                uint32_t b1 = Bs[cn][ck + 4];
                MMA_TF32(acc[0][nt], af[0], b0, b1);
                MMA_TF32(acc[1][nt], af[1], b0, b1);
            }
        }
        __syncthreads();
    }

#pragma unroll
    for (int mt = 0; mt < 2; mt++) {
#pragma unroll
        for (int nt = 0; nt < 4; nt++) {
            int row = m0 + wm + mt * 16 + (lane >> 2);
            int col = n0 + wn + nt * 8 + 2 * (lane & 3);
            float b0v = bias[col];
            float b1v = bias[col + 1];
            float v0 = acc[mt][nt][0] + b0v;
            float v1 = acc[mt][nt][1] + b1v;
            float v2 = acc[mt][nt][2] + b0v;
            float v3 = acc[mt][nt][3] + b1v;
            if (RELU) {
                v0 = fmaxf(v0, 0.f); v1 = fmaxf(v1, 0.f);
                v2 = fmaxf(v2, 0.f); v3 = fmaxf(v3, 0.f);
            }
            if (row < M)
                *(float2*)(C + (size_t)row * N + col) = make_float2(v0, v1);
            if (row + 8 < M)
                *(float2*)(C + (size_t)(row + 8) * N + col) = make_float2(v2, v3);
        }
    }
}

// ---------------------------------------------------------------------------
// Fused GEMM2 + GRU gates.
// gi = hidden @ w_ih^T + b_ih computed per block tile M=64 x N=192 (FULL gate
// width, so r/z/n columns are all block-local). gi tile staged transposed in
// smem, then gates computed in-epilogue: reads gh (precomputed), x; writes out.
// 8 warps as 2(m) x 4(n): warp tile 32x48 = mt 2 x nt 6.
// Dynamic smem: max(mainloop tiles 20.5KB, staging 192*68*4 = 52.2KB).
// ---------------------------------------------------------------------------
#define GF_SMEM_BYTES (192 * 68 * 4)

__global__ void __launch_bounds__(256) gemm2_gates(const float* __restrict__ A,    // hidden [M,256]
                                                   const float* __restrict__ B,    // w_ih [192,256]
                                                   const float* __restrict__ bias, // b_ih [192]
                                                   const float* __restrict__ gh,   // [M,192]
                                                   const float* __restrict__ x,    // [M,64]
                                                   float* __restrict__ out,        // [M,64]
                                                   int M) {
    extern __shared__ float smem[];
    uint32_t* As = (uint32_t*)smem;              // [64][20]
    uint32_t* Bs = As + 64 * 20;                 // [192][20]
    float*    gi_s = smem;                       // [192][68] (overlays tiles post-loop)

    const int tid  = threadIdx.x;
    const int lane = tid & 31;
    const int w    = tid >> 5;
    const int wm   = (w & 1) * 32;               // m offset in block (0/32)
    const int wn   = (w >> 1) * 48;              // n offset in block (0..144)
    const int m0   = blockIdx.x * 64;

    const int lrow = tid >> 2;                   // 0..63
    const int lcol = (tid & 3) * 4;              // 0,4,8,12

    float acc[2][6][4];
#pragma unroll
    for (int mt = 0; mt < 2; mt++)
#pragma unroll
        for (int nt = 0; nt < 6; nt++)
#pragma unroll
            for (int j = 0; j < 4; j++) acc[mt][nt][j] = 0.f;

    for (int k0 = 0; k0 < DH; k0 += 16) {
        // A tile 64x16 (1 float4 / thread)
        {
            int gm = m0 + lrow;
            float4 v = make_float4(0.f, 0.f, 0.f, 0.f);
            if (gm < M) v = *(const float4*)(A + (size_t)gm * DH + k0 + lcol);
            As[lrow * 20 + lcol + 0] = to_tf32(v.x);
            As[lrow * 20 + lcol + 1] = to_tf32(v.y);
            As[lrow * 20 + lcol + 2] = to_tf32(v.z);
            As[lrow * 20 + lcol + 3] = to_tf32(v.w);
        }
        // B tile 192x16 (3 float4 / thread)
#pragma unroll
        for (int p = 0; p < 3; p++) {
            int r = p * 64 + lrow;
            float4 v = *(const float4*)(B + (size_t)r * DH + k0 + lcol);
            Bs[r * 20 + lcol + 0] = to_tf32(v.x);
            Bs[r * 20 + lcol + 1] = to_tf32(v.y);
            Bs[r * 20 + lcol + 2] = to_tf32(v.z);
            Bs[r * 20 + lcol + 3] = to_tf32(v.w);
        }
        __syncthreads();

#pragma unroll
        for (int ks = 0; ks < 16; ks += 8) {
            uint32_t af[2][4];
#pragma unroll
            for (int mt = 0; mt < 2; mt++) {
                int r = wm + mt * 16 + (lane >> 2);
                int c = ks + (lane & 3);
                af[mt][0] = As[r * 20 + c];
                af[mt][1] = As[(r + 8) * 20 + c];
                af[mt][2] = As[r * 20 + c + 4];
                af[mt][3] = As[(r + 8) * 20 + c + 4];
            }
#pragma unroll
            for (int nt = 0; nt < 6; nt++) {
                int cn = wn + nt * 8 + (lane >> 2);
                int ck = ks + (lane & 3);
                uint32_t b0 = Bs[cn * 20 + ck];
                uint32_t b1 = Bs[cn * 20 + ck + 4];
                MMA_TF32(acc[0][nt], af[0], b0, b1);
                MMA_TF32(acc[1][nt], af[1], b0, b1);
            }
        }
        __syncthreads();   // last iteration: tiles fully consumed before overlay
    }

    // Stage gi tile transposed: gi_s[col][row], stride 68 (conflict-free writes)
#pragma unroll
    for (int mt = 0; mt < 2; mt++) {
#pragma unroll
        for (int nt = 0; nt < 6; nt++) {
            int rl  = wm + mt * 16 + (lane >> 2);
            int col = wn + nt * 8 + 2 * (lane & 3);
            float b0v = bias[col];
            float b1v = bias[col + 1];
            gi_s[col * 68 + rl]           = acc[mt][nt][0] + b0v;
            gi_s[(col + 1) * 68 + rl]     = acc[mt][nt][1] + b1v;
            gi_s[col * 68 + rl + 8]       = acc[mt][nt][2] + b0v;
            gi_s[(col + 1) * 68 + rl + 8] = acc[mt][nt][3] + b1v;
        }
    }
    __syncthreads();

    // Gates epilogue: thread -> (row r, 16 cols)
    {
        int r     = tid >> 2;            // 0..63
        int cbase = (tid & 3) * 16;      // 0,16,32,48
        int grow  = m0 + r;
        if (grow < M) {
            const float* ghrow = gh + (size_t)grow * G3;
            const float* xrow  = x  + (size_t)grow * DI;
            float*       orow  = out + (size_t)grow * DI;
#pragma unroll
            for (int j = 0; j < 16; j++) {
                int c = cbase + j;
                float ir  = gi_s[c * 68 + r];
                float iz  = gi_s[(c + 64) * 68 + r];
                float in_ = gi_s[(c + 128) * 68 + r];
                float hr = ghrow[c];
                float hz = ghrow[c + 64];
                float hn = ghrow[c + 128];
                float rg = sigmoidf_(ir + hr);
                float zg = sigmoidf_(iz + hz);
                float ng = tanhf(in_ + rg * hn);
                orow[c] = (1.f - zg) * ng + zg * xrow[c];
            }
        }
    }
}

// ---------------------------------------------------------------------------
// Launch
// ---------------------------------------------------------------------------
extern "C" void kernel_launch(void* const* d_in, const int* in_sizes, int n_in,
                              void* d_out, int out_size) {
    const float* x     = (const float*)d_in[0];      // [NN, 64]
    const void*  eidx  = d_in[1];                    // [2, NE] int32 or int64
    const void*  etype = d_in[2];                    // [NE]
    const float* ew    = (const float*)d_in[3];      // [NE]
    const float* mlpW  = (const float*)d_in[4];      // [256, 256]
    const float* mlpb  = (const float*)d_in[5];      // [256]
    const float* wih   = (const float*)d_in[6];      // [192, 256]
    const float* whh   = (const float*)d_in[7];      // [192, 64]
    const float* bih   = (const float*)d_in[8];      // [192]
    const float* bhh   = (const float*)d_in[9];      // [192]
    float*       out   = (float*)d_out;              // [NN, 64]

    float *upd, *hid, *gh;
    cudaGetSymbolAddress((void**)&upd, g_update);
    cudaGetSymbolAddress((void**)&hid, g_hidden);
    cudaGetSymbolAddress((void**)&gh,  g_gh);

    cudaFuncSetAttribute(gemm2_gates,
                         cudaFuncAttributeMaxDynamicSharedMemorySize,
                         GF_SMEM_BYTES);

    const int MB128 = (NN + 127) / 128;   // 782
    const int MB64  = (NN + 63) / 64;     // 1563

    // 0) dtype probe + index normalization
    flag_reset_kernel<<<1, 1>>>();
    probe_kernel<<<16, 256>>>((const long long*)eidx);
    convert_kernel<<<(NE + 255) / 256, 256>>>(eidx, etype);

    // 1) zero accumulator
    zero_kernel<<<25000, 256>>>((float4*)upd, 6400000);

    // 2) edge scatter (vectorized L2 reductions)
    scatter_kernel<<<(NE * 16) / 256, 256>>>(x, ew, upd);

    // 3) hidden = relu(update @ mlpW^T + mlpb)   [NN,256]
    //    grid.x = N-blocks so CTAs sharing an A tile are co-resident (L2 reuse)
    gemm_tf32<KU, 1><<<dim3(DH / 64, MB128), 256>>>(upd, mlpW, mlpb, hid, NN, DH);

    // 4) gh = x @ w_hh^T + b_hh                  [NN,192]
    gemm_tf32<DI, 0><<<dim3(G3 / 64, MB128), 256>>>(x, whh, bhh, gh, NN, G3);

    // 5) fused: gi = hidden @ w_ih^T + b_ih, then GRU gates -> out
    gemm2_gates<<<MB64, 256, GF_SMEM_BYTES>>>(hid, wih, bih, gh, x, out, NN);
}

// round 8
// speedup vs baseline: 1.1984x; 1.1984x over previous
#include <cuda_runtime.h>
#include <cuda_bf16.h>
#include <math.h>
#include <stdint.h>

// Problem constants (shapes fixed by the dataset)
#define NN 100000           // nodes
#define NE 1000000          // edges
#define ET 4                // edge types
#define DI 64               // input dim
#define DH 256              // hidden dim
#define KU (ET*DI)          // 256 = update row width
#define G3 (3*DI)           // 192 = gate width

// Scratch (device globals — allocation-free)
__device__ float g_update[(size_t)NN * KU];   // 102.4 MB
__device__ float g_hidden[(size_t)NN * DH];   // 102.4 MB
__device__ float g_gi[(size_t)NN * G3];       // 76.8 MB
__device__ float g_gh[(size_t)NN * G3];       // 76.8 MB
__device__ int   g_src[NE];
__device__ int   g_dst[NE];
__device__ int   g_typ[NE];
__device__ int   g_is_i32;                    // 1 => edge arrays are int32

// ---------------------------------------------------------------------------
// Index-dtype probe (known good)
// ---------------------------------------------------------------------------
__global__ void flag_reset_kernel() { g_is_i32 = 0; }

__global__ void probe_kernel(const long long* __restrict__ eidx) {
    int i = blockIdx.x * blockDim.x + threadIdx.x;   // 4096 probes
    long long v = eidx[i];
    if (v < 0 || v >= (long long)NN) atomicExch(&g_is_i32, 1);
}

__global__ void convert_kernel(const void* __restrict__ eidx,
                               const void* __restrict__ etype) {
    int e = blockIdx.x * blockDim.x + threadIdx.x;
    if (e >= NE) return;
    if (g_is_i32) {
        const int* p = (const int*)eidx;
        g_src[e] = p[e];
        g_dst[e] = p[NE + e];
        g_typ[e] = ((const int*)etype)[e];
    } else {
        const long long* p = (const long long*)eidx;
        g_src[e] = (int)p[e];
        g_dst[e] = (int)p[NE + e];
        g_typ[e] = (int)((const long long*)etype)[e];
    }
}

// ---------------------------------------------------------------------------
// Zero the update accumulator
// ---------------------------------------------------------------------------
__global__ void zero_kernel(float4* __restrict__ p, int n4) {
    int i = blockIdx.x * blockDim.x + threadIdx.x;
    if (i < n4) p[i] = make_float4(0.f, 0.f, 0.f, 0.f);
}

// ---------------------------------------------------------------------------
// Edge scatter with vectorized L2 reduction (known good)
// ---------------------------------------------------------------------------
__global__ void scatter_kernel(const float* __restrict__ x,
                               const float* __restrict__ ew,
                               float* __restrict__ upd) {
    int i = blockIdx.x * blockDim.x + threadIdx.x;   // NE*16 work items
    int e = i >> 4;
    int c = i & 15;
    if (e >= NE) return;
    int src = g_src[e];
    int dst = g_dst[e];
    int t   = g_typ[e];
    if ((unsigned)src >= NN || (unsigned)dst >= NN || (unsigned)t >= ET) return;
    float w = ew[e];
    float4 v = *(const float4*)(x + (size_t)src * DI + c * 4);
    float* drow = upd + ((size_t)dst * ET + t) * DI + c * 4;
    asm volatile("red.global.add.v4.f32 [%0], {%1,%2,%3,%4};"
                 :: "l"(drow), "f"(w * v.x), "f"(w * v.y),
                    "f"(w * v.z), "f"(w * v.w)
                 : "memory");
}

// ---------------------------------------------------------------------------
// TF32 mma helpers
// ---------------------------------------------------------------------------
#define MMA_TF32(d, a, b0, b1)                                                 \
    asm volatile(                                                              \
        "mma.sync.aligned.m16n8k8.row.col.f32.tf32.tf32.f32 "                  \
        "{%0,%1,%2,%3},{%4,%5,%6,%7},{%8,%9},{%0,%1,%2,%3};"                   \
        : "+f"((d)[0]), "+f"((d)[1]), "+f"((d)[2]), "+f"((d)[3])               \
        : "r"((a)[0]), "r"((a)[1]), "r"((a)[2]), "r"((a)[3]),                  \
          "r"(b0), "r"(b1))

__device__ __forceinline__ uint32_t to_tf32(float v) {
    uint32_t u;
    asm("cvt.rna.tf32.f32 %0, %1;" : "=r"(u) : "f"(v));
    return u;
}

__device__ __forceinline__ uint32_t smem_u32(const void* p) {
    return (uint32_t)__cvta_generic_to_shared(p);
}

// ---------------------------------------------------------------------------
// TF32 GEMM with cp.async double-buffered pipeline.
// C[M,N] = epi(A[M,K] @ B[N,K]^T + bias[N])
// Block 128x64, 8 warps (4x2), warp tile 32x32, BK=16, 2 stages.
// fp32 staged raw in smem via cp.async; cvt.rna to tf32 at fragment build.
// ---------------------------------------------------------------------------
template<int K, int RELU>
__global__ void __launch_bounds__(256) gemm_tf32(const float* __restrict__ A,
                                                 const float* __restrict__ B,
                                                 const float* __restrict__ bias,
                                                 float* __restrict__ C,
                                                 int M, int N) {
    __shared__ float As[2][128][20];
    __shared__ float Bs[2][64][20];

    const int tid  = threadIdx.x;
    const int lane = tid & 31;
    const int w    = tid >> 5;
    const int wm   = (w & 3) * 32;
    const int wn   = (w >> 2) * 32;
    const int m0   = blockIdx.x * 128;
    const int n0   = blockIdx.y * 64;

    const int lrow = tid >> 2;         // 0..63
    const int lcol = (tid & 3) * 4;    // 0,4,8,12

    const int niter = K / 16;

    // issue cp.async for tile `it` into stage `s`
    auto issue_tile = [&](int it, int s) {
        int k0 = it * 16;
#pragma unroll
        for (int p = 0; p < 2; p++) {
            int r  = p * 64 + lrow;
            int gm = m0 + r;
            const float* src = A + (size_t)gm * K + k0 + lcol;
            uint32_t dst = smem_u32(&As[s][r][lcol]);
            int sz = (gm < M) ? 16 : 0;   // zero-fill OOB rows
            asm volatile("cp.async.cg.shared.global [%0], [%1], 16, %2;"
                         :: "r"(dst), "l"(src), "r"(sz));
        }
        {
            const float* src = B + (size_t)(n0 + lrow) * K + k0 + lcol;
            uint32_t dst = smem_u32(&Bs[s][lrow][lcol]);
            asm volatile("cp.async.cg.shared.global [%0], [%1], 16;"
                         :: "r"(dst), "l"(src));
        }
    };

    float acc[2][4][4];
#pragma unroll
    for (int mt = 0; mt < 2; mt++)
#pragma unroll
        for (int nt = 0; nt < 4; nt++)
#pragma unroll
            for (int j = 0; j < 4; j++) acc[mt][nt][j] = 0.f;

    issue_tile(0, 0);
    asm volatile("cp.async.commit_group;");

    for (int i = 0; i < niter; i++) {
        if (i + 1 < niter) issue_tile(i + 1, (i + 1) & 1);
        asm volatile("cp.async.commit_group;");
        asm volatile("cp.async.wait_group 1;");   // tile i resident
        __syncthreads();

        const int s = i & 1;
#pragma unroll
        for (int ks = 0; ks < 16; ks += 8) {
            uint32_t af[2][4];
#pragma unroll
            for (int mt = 0; mt < 2; mt++) {
                int r = wm + mt * 16 + (lane >> 2);
                int c = ks + (lane & 3);
                af[mt][0] = to_tf32(As[s][r][c]);
                af[mt][1] = to_tf32(As[s][r + 8][c]);
                af[mt][2] = to_tf32(As[s][r][c + 4]);
                af[mt][3] = to_tf32(As[s][r + 8][c + 4]);
            }
#pragma unroll
            for (int nt = 0; nt < 4; nt++) {
                int cn = wn + nt * 8 + (lane >> 2);
                int ck = ks + (lane & 3);
                uint32_t b0 = to_tf32(Bs[s][cn][ck]);
                uint32_t b1 = to_tf32(Bs[s][cn][ck + 4]);
                MMA_TF32(acc[0][nt], af[0], b0, b1);
                MMA_TF32(acc[1][nt], af[1], b0, b1);
            }
        }
        __syncthreads();   // protect stage s before it is refilled at iter i+2
    }

    // Epilogue
#pragma unroll
    for (int mt = 0; mt < 2; mt++) {
#pragma unroll
        for (int nt = 0; nt < 4; nt++) {
            int row = m0 + wm + mt * 16 + (lane >> 2);
            int col = n0 + wn + nt * 8 + 2 * (lane & 3);
            float b0v = bias[col];
            float b1v = bias[col + 1];
            float v0 = acc[mt][nt][0] + b0v;
            float v1 = acc[mt][nt][1] + b1v;
            float v2 = acc[mt][nt][2] + b0v;
            float v3 = acc[mt][nt][3] + b1v;
            if (RELU) {
                v0 = fmaxf(v0, 0.f); v1 = fmaxf(v1, 0.f);
                v2 = fmaxf(v2, 0.f); v3 = fmaxf(v3, 0.f);
            }
            if (row < M)
                *(float2*)(C + (size_t)row * N + col) = make_float2(v0, v1);
            if (row + 8 < M)
                *(float2*)(C + (size_t)(row + 8) * N + col) = make_float2(v2, v3);
        }
    }
}

// ---------------------------------------------------------------------------
// GRU gate epilogue: out = (1-z)*n + z*h
// ---------------------------------------------------------------------------
__global__ void gates_kernel(const float* __restrict__ x,
                             const float* __restrict__ gi,
                             const float* __restrict__ gh,
                             float* __restrict__ out) {
    int i = blockIdx.x * blockDim.x + threadIdx.x;   // NN*DI
    if (i >= NN * DI) return;
    int m = i >> 6;
    int d = i & 63;
    const float* gim = gi + (size_t)m * G3;
    const float* ghm = gh + (size_t)m * G3;
    float ir  = gim[d],        hr = ghm[d];
    float iz  = gim[64 + d],   hz = ghm[64 + d];
    float in_ = gim[128 + d],  hn = ghm[128 + d];
    float r = 1.f / (1.f + expf(-(ir + hr)));
    float z = 1.f / (1.f + expf(-(iz + hz)));
    float n = tanhf(in_ + r * hn);
    float h = x[i];
    out[i] = (1.f - z) * n + z * h;
}

// ---------------------------------------------------------------------------
// Launch (R6 structure: separate GEMMs + gates, m-fastest grids)
// ---------------------------------------------------------------------------
extern "C" void kernel_launch(void* const* d_in, const int* in_sizes, int n_in,
                              void* d_out, int out_size) {
    const float* x     = (const float*)d_in[0];      // [NN, 64]
    const void*  eidx  = d_in[1];                    // [2, NE] int32 or int64
    const void*  etype = d_in[2];                    // [NE]
    const float* ew    = (const float*)d_in[3];      // [NE]
    const float* mlpW  = (const float*)d_in[4];      // [256, 256]
    const float* mlpb  = (const float*)d_in[5];      // [256]
    const float* wih   = (const float*)d_in[6];      // [192, 256]
    const float* whh   = (const float*)d_in[7];      // [192, 64]
    const float* bih   = (const float*)d_in[8];      // [192]
    const float* bhh   = (const float*)d_in[9];      // [192]
    float*       out   = (float*)d_out;              // [NN, 64]

    float *upd, *hid, *gi, *gh;
    cudaGetSymbolAddress((void**)&upd, g_update);
    cudaGetSymbolAddress((void**)&hid, g_hidden);
    cudaGetSymbolAddress((void**)&gi,  g_gi);
    cudaGetSymbolAddress((void**)&gh,  g_gh);

    const int MB128 = (NN + 127) / 128;   // 782

    // 0) dtype probe + index normalization
    flag_reset_kernel<<<1, 1>>>();
    probe_kernel<<<16, 256>>>((const long long*)eidx);
    convert_kernel<<<(NE + 255) / 256, 256>>>(eidx, etype);

    // 1) zero accumulator
    zero_kernel<<<25000, 256>>>((float4*)upd, 6400000);

    // 2) edge scatter (vectorized L2 reductions)
    scatter_kernel<<<(NE * 16) / 256, 256>>>(x, ew, upd);

    // 3) hidden = relu(update @ mlpW^T + mlpb)   [NN,256]
    gemm_tf32<KU, 1><<<dim3(MB128, DH / 64), 256>>>(upd, mlpW, mlpb, hid, NN, DH);

    // 4) gi = hidden @ w_ih^T + b_ih             [NN,192]
    gemm_tf32<DH, 0><<<dim3(MB128, G3 / 64), 256>>>(hid, wih, bih, gi, NN, G3);

    // 5) gh = x @ w_hh^T + b_hh                  [NN,192]
    gemm_tf32<DI, 0><<<dim3(MB128, G3 / 64), 256>>>(x, whh, bhh, gh, NN, G3);

    // 6) GRU gates -> out
    gates_kernel<<<(NN * DI) / 256, 256>>>(x, gi, gh, out);
}

// round 9
// speedup vs baseline: 1.2427x; 1.0369x over previous
#include <cuda_runtime.h>
#include <cuda_bf16.h>
#include <math.h>
#include <stdint.h>

// Problem constants (shapes fixed by the dataset)
#define NN 100000           // nodes
#define NE 1000000          // edges
#define ET 4                // edge types
#define DI 64               // input dim
#define DH 256              // hidden dim
#define KU (ET*DI)          // 256 = update row width
#define G3 (3*DI)           // 192 = gate width

// Scratch (device globals — allocation-free)
__device__ float g_update[(size_t)NN * KU];   // 102.4 MB
__device__ float g_hidden[(size_t)NN * DH];   // 102.4 MB
__device__ float g_gi[(size_t)NN * G3];       // 76.8 MB
__device__ float g_gh[(size_t)NN * G3];       // 76.8 MB
__device__ int   g_src[NE];
__device__ int   g_dst[NE];
__device__ int   g_typ[NE];
__device__ int   g_is_i32;                    // 1 => edge arrays are int32

// Pre-rounded (tf32) weight copies
#define WOFF_MLP 0
#define WOFF_IH  (DH*KU)                   // 65536
#define WOFF_HH  (WOFF_IH + G3*DH)         // 114688
#define WTOTAL   (WOFF_HH + G3*DI)         // 126976
__device__ float g_wbuf[WTOTAL];

// ---------------------------------------------------------------------------
// Index-dtype probe (known good)
// ---------------------------------------------------------------------------
__global__ void flag_reset_kernel() { g_is_i32 = 0; }

__global__ void probe_kernel(const long long* __restrict__ eidx) {
    int i = blockIdx.x * blockDim.x + threadIdx.x;   // 4096 probes
    long long v = eidx[i];
    if (v < 0 || v >= (long long)NN) atomicExch(&g_is_i32, 1);
}

__global__ void convert_kernel(const void* __restrict__ eidx,
                               const void* __restrict__ etype) {
    int e = blockIdx.x * blockDim.x + threadIdx.x;
    if (e >= NE) return;
    if (g_is_i32) {
        const int* p = (const int*)eidx;
        g_src[e] = p[e];
        g_dst[e] = p[NE + e];
        g_typ[e] = ((const int*)etype)[e];
    } else {
        const long long* p = (const long long*)eidx;
        g_src[e] = (int)p[e];
        g_dst[e] = (int)p[NE + e];
        g_typ[e] = (int)((const long long*)etype)[e];
    }
}

// ---------------------------------------------------------------------------
// tf32 helpers
// ---------------------------------------------------------------------------
__device__ __forceinline__ uint32_t to_tf32(float v) {
    uint32_t u;
    asm("cvt.rna.tf32.f32 %0, %1;" : "=r"(u) : "f"(v));
    return u;
}

// Pre-round weights into scratch (one-time, ~127K elements)
__global__ void round_weights_kernel(const float* __restrict__ mlpW,
                                     const float* __restrict__ wih,
                                     const float* __restrict__ whh) {
    int i = blockIdx.x * blockDim.x + threadIdx.x;
    if (i >= WTOTAL) return;
    float v;
    if (i < WOFF_IH)       v = mlpW[i];
    else if (i < WOFF_HH)  v = wih[i - WOFF_IH];
    else                   v = whh[i - WOFF_HH];
    g_wbuf[i] = __uint_as_float(to_tf32(v));
}

// ---------------------------------------------------------------------------
// Zero the update accumulator
// ---------------------------------------------------------------------------
__global__ void zero_kernel(float4* __restrict__ p, int n4) {
    int i = blockIdx.x * blockDim.x + threadIdx.x;
    if (i < n4) p[i] = make_float4(0.f, 0.f, 0.f, 0.f);
}

// ---------------------------------------------------------------------------
// Edge scatter with vectorized L2 reduction (known good)
// ---------------------------------------------------------------------------
__global__ void scatter_kernel(const float* __restrict__ x,
                               const float* __restrict__ ew,
                               float* __restrict__ upd) {
    int i = blockIdx.x * blockDim.x + threadIdx.x;   // NE*16 work items
    int e = i >> 4;
    int c = i & 15;
    if (e >= NE) return;
    int src = g_src[e];
    int dst = g_dst[e];
    int t   = g_typ[e];
    if ((unsigned)src >= NN || (unsigned)dst >= NN || (unsigned)t >= ET) return;
    float w = ew[e];
    float4 v = *(const float4*)(x + (size_t)src * DI + c * 4);
    float* drow = upd + ((size_t)dst * ET + t) * DI + c * 4;
    asm volatile("red.global.add.v4.f32 [%0], {%1,%2,%3,%4};"
                 :: "l"(drow), "f"(w * v.x), "f"(w * v.y),
                    "f"(w * v.z), "f"(w * v.w)
                 : "memory");
}

// ---------------------------------------------------------------------------
// TF32 mma
// ---------------------------------------------------------------------------
#define MMA_TF32(d, a, b0, b1)                                                 \
    asm volatile(                                                              \
        "mma.sync.aligned.m16n8k8.row.col.f32.tf32.tf32.f32 "                  \
        "{%0,%1,%2,%3},{%4,%5,%6,%7},{%8,%9},{%0,%1,%2,%3};"                   \
        : "+f"((d)[0]), "+f"((d)[1]), "+f"((d)[2]), "+f"((d)[3])               \
        : "r"((a)[0]), "r"((a)[1]), "r"((a)[2]), "r"((a)[3]),                  \
          "r"(b0), "r"(b1))

__device__ __forceinline__ uint32_t smem_u32(const void* p) {
    return (uint32_t)__cvta_generic_to_shared(p);
}

// ---------------------------------------------------------------------------
// TF32 GEMM, 3-stage cp.async pipeline, one __syncthreads per K-iter.
// C[M,N] = epi(A[M,K] @ B[N,K]^T + bias[N])
// Block 128x64, 8 warps (4x2), warp tile 32x32, BK=16.
// B is pre-rounded tf32 (no cvt). A cvt only if CVT_A.
// CVT_OUT: round output to tf32 (so the next GEMM can skip its A cvt).
// ---------------------------------------------------------------------------
template<int K, int RELU, int CVT_A, int CVT_OUT>
__global__ void __launch_bounds__(256) gemm_tf32(const float* __restrict__ A,
                                                 const float* __restrict__ B,
                                                 const float* __restrict__ bias,
                                                 float* __restrict__ C,
                                                 int M, int N) {
    __shared__ float As[3][128][20];
    __shared__ float Bs[3][64][20];

    const int tid  = threadIdx.x;
    const int lane = tid & 31;
    const int w    = tid >> 5;
    const int wm   = (w & 3) * 32;
    const int wn   = (w >> 2) * 32;
    const int m0   = blockIdx.x * 128;
    const int n0   = blockIdx.y * 64;

    const int lrow = tid >> 2;         // 0..63
    const int lcol = (tid & 3) * 4;    // 0,4,8,12

    const int niter = K / 16;

    auto issue_tile = [&](int it, int s) {
        int k0 = it * 16;
#pragma unroll
        for (int p = 0; p < 2; p++) {
            int r  = p * 64 + lrow;
            int gm = m0 + r;
            const float* src = A + (size_t)gm * K + k0 + lcol;
            uint32_t dst = smem_u32(&As[s][r][lcol]);
            int sz = (gm < M) ? 16 : 0;   // zero-fill OOB rows
            asm volatile("cp.async.cg.shared.global [%0], [%1], 16, %2;"
                         :: "r"(dst), "l"(src), "r"(sz));
        }
        {
            const float* src = B + (size_t)(n0 + lrow) * K + k0 + lcol;
            uint32_t dst = smem_u32(&Bs[s][lrow][lcol]);
            asm volatile("cp.async.cg.shared.global [%0], [%1], 16;"
                         :: "r"(dst), "l"(src));
        }
    };

    float acc[2][4][4];
#pragma unroll
    for (int mt = 0; mt < 2; mt++)
#pragma unroll
        for (int nt = 0; nt < 4; nt++)
#pragma unroll
            for (int j = 0; j < 4; j++) acc[mt][nt][j] = 0.f;

    // Prologue: tiles 0 and 1 in flight
    issue_tile(0, 0);
    asm volatile("cp.async.commit_group;");
    if (niter > 1) issue_tile(1, 1);
    asm volatile("cp.async.commit_group;");

    int s = 0, s2 = 2;   // compute stage, refill stage (i+2)%3
    for (int i = 0; i < niter; i++) {
        asm volatile("cp.async.wait_group 1;");   // tile i resident
        __syncthreads();                          // all done with tile i-1's stage

        if (i + 2 < niter) issue_tile(i + 2, s2);
        asm volatile("cp.async.commit_group;");

#pragma unroll
        for (int ks = 0; ks < 16; ks += 8) {
            uint32_t af[2][4];
#pragma unroll
            for (int mt = 0; mt < 2; mt++) {
                int r = wm + mt * 16 + (lane >> 2);
                int c = ks + (lane & 3);
                if (CVT_A) {
                    af[mt][0] = to_tf32(As[s][r][c]);
                    af[mt][1] = to_tf32(As[s][r + 8][c]);
                    af[mt][2] = to_tf32(As[s][r][c + 4]);
                    af[mt][3] = to_tf32(As[s][r + 8][c + 4]);
                } else {
                    af[mt][0] = __float_as_uint(As[s][r][c]);
                    af[mt][1] = __float_as_uint(As[s][r + 8][c]);
                    af[mt][2] = __float_as_uint(As[s][r][c + 4]);
                    af[mt][3] = __float_as_uint(As[s][r + 8][c + 4]);
                }
            }
#pragma unroll
            for (int nt = 0; nt < 4; nt++) {
                int cn = wn + nt * 8 + (lane >> 2);
                int ck = ks + (lane & 3);
                uint32_t b0 = __float_as_uint(Bs[s][cn][ck]);
                uint32_t b1 = __float_as_uint(Bs[s][cn][ck + 4]);
                MMA_TF32(acc[0][nt], af[0], b0, b1);
                MMA_TF32(acc[1][nt], af[1], b0, b1);
            }
        }
        s  = (s  == 2) ? 0 : s  + 1;
        s2 = (s2 == 2) ? 0 : s2 + 1;
    }

    // Epilogue
#pragma unroll
    for (int mt = 0; mt < 2; mt++) {
#pragma unroll
        for (int nt = 0; nt < 4; nt++) {
            int row = m0 + wm + mt * 16 + (lane >> 2);
            int col = n0 + wn + nt * 8 + 2 * (lane & 3);
            float b0v = bias[col];
            float b1v = bias[col + 1];
            float v0 = acc[mt][nt][0] + b0v;
            float v1 = acc[mt][nt][1] + b1v;
            float v2 = acc[mt][nt][2] + b0v;
            float v3 = acc[mt][nt][3] + b1v;
            if (RELU) {
                v0 = fmaxf(v0, 0.f); v1 = fmaxf(v1, 0.f);
                v2 = fmaxf(v2, 0.f); v3 = fmaxf(v3, 0.f);
            }
            if (CVT_OUT) {
                v0 = __uint_as_float(to_tf32(v0));
                v1 = __uint_as_float(to_tf32(v1));
                v2 = __uint_as_float(to_tf32(v2));
                v3 = __uint_as_float(to_tf32(v3));
            }
            if (row < M)
                *(float2*)(C + (size_t)row * N + col) = make_float2(v0, v1);
            if (row + 8 < M)
                *(float2*)(C + (size_t)(row + 8) * N + col) = make_float2(v2, v3);
        }
    }
}

// ---------------------------------------------------------------------------
// GRU gate epilogue: out = (1-z)*n + z*h
// ---------------------------------------------------------------------------
__global__ void gates_kernel(const float* __restrict__ x,
                             const float* __restrict__ gi,
                             const float* __restrict__ gh,
                             float* __restrict__ out) {
    int i = blockIdx.x * blockDim.x + threadIdx.x;   // NN*DI
    if (i >= NN * DI) return;
    int m = i >> 6;
    int d = i & 63;
    const float* gim = gi + (size_t)m * G3;
    const float* ghm = gh + (size_t)m * G3;
    float ir  = gim[d],        hr = ghm[d];
    float iz  = gim[64 + d],   hz = ghm[64 + d];
    float in_ = gim[128 + d],  hn = ghm[128 + d];
    float r = 1.f / (1.f + expf(-(ir + hr)));
    float z = 1.f / (1.f + expf(-(iz + hz)));
    float n = tanhf(in_ + r * hn);
    float h = x[i];
    out[i] = (1.f - z) * n + z * h;
}

// ---------------------------------------------------------------------------
// Launch
// ---------------------------------------------------------------------------
extern "C" void kernel_launch(void* const* d_in, const int* in_sizes, int n_in,
                              void* d_out, int out_size) {
    const float* x     = (const float*)d_in[0];      // [NN, 64]
    const void*  eidx  = d_in[1];                    // [2, NE] int32 or int64
    const void*  etype = d_in[2];                    // [NE]
    const float* ew    = (const float*)d_in[3];      // [NE]
    const float* mlpW  = (const float*)d_in[4];      // [256, 256]
    const float* mlpb  = (const float*)d_in[5];      // [256]
    const float* wih   = (const float*)d_in[6];      // [192, 256]
    const float* whh   = (const float*)d_in[7];      // [192, 64]
    const float* bih   = (const float*)d_in[8];      // [192]
    const float* bhh   = (const float*)d_in[9];      // [192]
    float*       out   = (float*)d_out;              // [NN, 64]

    float *upd, *hid, *gi, *gh, *wbuf;
    cudaGetSymbolAddress((void**)&upd, g_update);
    cudaGetSymbolAddress((void**)&hid, g_hidden);
    cudaGetSymbolAddress((void**)&gi,  g_gi);
    cudaGetSymbolAddress((void**)&gh,  g_gh);
    cudaGetSymbolAddress((void**)&wbuf, g_wbuf);

    const int MB128 = (NN + 127) / 128;   // 782

    // 0) dtype probe + index normalization + weight pre-rounding
    flag_reset_kernel<<<1, 1>>>();
    probe_kernel<<<16, 256>>>((const long long*)eidx);
    convert_kernel<<<(NE + 255) / 256, 256>>>(eidx, etype);
    round_weights_kernel<<<WTOTAL / 256, 256>>>(mlpW, wih, whh);

    // 1) zero accumulator
    zero_kernel<<<25000, 256>>>((float4*)upd, 6400000);

    // 2) edge scatter (vectorized L2 reductions)
    scatter_kernel<<<(NE * 16) / 256, 256>>>(x, ew, upd);

    // 3) hidden = relu(update @ mlpW^T + mlpb), output rounded to tf32
    gemm_tf32<KU, 1, 1, 1><<<dim3(MB128, DH / 64), 256>>>(
        upd, wbuf + WOFF_MLP, mlpb, hid, NN, DH);

    // 4) gi = hidden @ w_ih^T + b_ih   (A already tf32 -> no cvt in loop)
    gemm_tf32<DH, 0, 0, 0><<<dim3(MB128, G3 / 64), 256>>>(
        hid, wbuf + WOFF_IH, bih, gi, NN, G3);

    // 5) gh = x @ w_hh^T + b_hh        (A raw fp32 -> cvt)
    gemm_tf32<DI, 0, 1, 0><<<dim3(MB128, G3 / 64), 256>>>(
        x, wbuf + WOFF_HH, bhh, gh, NN, G3);

    // 6) GRU gates -> out
    gates_kernel<<<(NN * DI) / 256, 256>>>(x, gi, gh, out);
}

// round 10
// speedup vs baseline: 1.3037x; 1.0491x over previous
#include <cuda_runtime.h>
#include <cuda_bf16.h>
#include <math.h>
#include <stdint.h>

// Problem constants (shapes fixed by the dataset)
#define NN 100000           // nodes
#define NE 1000000          // edges
#define ET 4                // edge types
#define DI 64               // input dim
#define DH 256              // hidden dim
#define KU (ET*DI)          // 256 = update row width
#define G3 (3*DI)           // 192 = gate width

// Scratch (device globals — allocation-free)
__device__ float g_update[(size_t)NN * KU];   // 102.4 MB
__device__ float g_hidden[(size_t)NN * DH];   // 102.4 MB
__device__ float g_gi[(size_t)NN * G3];       // 76.8 MB
__device__ float g_gh[(size_t)NN * G3];       // 76.8 MB
__device__ int   g_src[NE];
__device__ int   g_dst[NE];
__device__ int   g_typ[NE];
__device__ int   g_is_i32;                    // 1 => edge arrays are int32

// Pre-rounded (tf32) weight copies
#define WOFF_MLP 0
#define WOFF_IH  (DH*KU)                   // 65536
#define WOFF_HH  (WOFF_IH + G3*DH)         // 114688
#define WTOTAL   (WOFF_HH + G3*DI)         // 126976
__device__ float g_wbuf[WTOTAL];

// ---------------------------------------------------------------------------
// Index-dtype probe (known good)
// ---------------------------------------------------------------------------
__global__ void flag_reset_kernel() { g_is_i32 = 0; }

__global__ void probe_kernel(const long long* __restrict__ eidx) {
    int i = blockIdx.x * blockDim.x + threadIdx.x;   // 4096 probes
    long long v = eidx[i];
    if (v < 0 || v >= (long long)NN) atomicExch(&g_is_i32, 1);
}

__global__ void convert_kernel(const void* __restrict__ eidx,
                               const void* __restrict__ etype) {
    int e = blockIdx.x * blockDim.x + threadIdx.x;
    if (e >= NE) return;
    if (g_is_i32) {
        const int* p = (const int*)eidx;
        g_src[e] = p[e];
        g_dst[e] = p[NE + e];
        g_typ[e] = ((const int*)etype)[e];
    } else {
        const long long* p = (const long long*)eidx;
        g_src[e] = (int)p[e];
        g_dst[e] = (int)p[NE + e];
        g_typ[e] = (int)((const long long*)etype)[e];
    }
}

// ---------------------------------------------------------------------------
// tf32 helpers
// ---------------------------------------------------------------------------
__device__ __forceinline__ uint32_t to_tf32(float v) {
    uint32_t u;
    asm("cvt.rna.tf32.f32 %0, %1;" : "=r"(u) : "f"(v));
    return u;
}

__global__ void round_weights_kernel(const float* __restrict__ mlpW,
                                     const float* __restrict__ wih,
                                     const float* __restrict__ whh) {
    int i = blockIdx.x * blockDim.x + threadIdx.x;
    if (i >= WTOTAL) return;
    float v;
    if (i < WOFF_IH)       v = mlpW[i];
    else if (i < WOFF_HH)  v = wih[i - WOFF_IH];
    else                   v = whh[i - WOFF_HH];
    g_wbuf[i] = __uint_as_float(to_tf32(v));
}

// ---------------------------------------------------------------------------
// Zero the update accumulator
// ---------------------------------------------------------------------------
__global__ void zero_kernel(float4* __restrict__ p, int n4) {
    int i = blockIdx.x * blockDim.x + threadIdx.x;
    if (i < n4) p[i] = make_float4(0.f, 0.f, 0.f, 0.f);
}

// ---------------------------------------------------------------------------
// Edge scatter with vectorized L2 reduction (known good)
// ---------------------------------------------------------------------------
__global__ void scatter_kernel(const float* __restrict__ x,
                               const float* __restrict__ ew,
                               float* __restrict__ upd) {
    int i = blockIdx.x * blockDim.x + threadIdx.x;   // NE*16 work items
    int e = i >> 4;
    int c = i & 15;
    if (e >= NE) return;
    int src = g_src[e];
    int dst = g_dst[e];
    int t   = g_typ[e];
    if ((unsigned)src >= NN || (unsigned)dst >= NN || (unsigned)t >= ET) return;
    float w = ew[e];
    float4 v = *(const float4*)(x + (size_t)src * DI + c * 4);
    float* drow = upd + ((size_t)dst * ET + t) * DI + c * 4;
    asm volatile("red.global.add.v4.f32 [%0], {%1,%2,%3,%4};"
                 :: "l"(drow), "f"(w * v.x), "f"(w * v.y),
                    "f"(w * v.z), "f"(w * v.w)
                 : "memory");
}

// ---------------------------------------------------------------------------
// TF32 mma
// ---------------------------------------------------------------------------
#define MMA_TF32(d, a, b0, b1)                                                 \
    asm volatile(                                                              \
        "mma.sync.aligned.m16n8k8.row.col.f32.tf32.tf32.f32 "                  \
        "{%0,%1,%2,%3},{%4,%5,%6,%7},{%8,%9},{%0,%1,%2,%3};"                   \
        : "+f"((d)[0]), "+f"((d)[1]), "+f"((d)[2]), "+f"((d)[3])               \
        : "r"((a)[0]), "r"((a)[1]), "r"((a)[2]), "r"((a)[3]),                  \
          "r"(b0), "r"(b1))

__device__ __forceinline__ uint32_t smem_u32(const void* p) {
    return (uint32_t)__cvta_generic_to_shared(p);
}

// ---------------------------------------------------------------------------
// TF32 GEMM, BK=32, 3-stage cp.async pipeline, one __syncthreads per K-iter.
// C[M,N] = epi(A[M,K] @ B[N,K]^T + bias[N])
// Block 128x64, 8 warps (4x2), warp tile 32x32.
// B pre-rounded tf32 (no cvt). A cvt only if CVT_A. CVT_OUT rounds output.
// K multiple of 32 required (256, 256, 64 all qualify).
// ---------------------------------------------------------------------------
template<int K, int RELU, int CVT_A, int CVT_OUT>
__global__ void __launch_bounds__(256) gemm_tf32(const float* __restrict__ A,
                                                 const float* __restrict__ B,
                                                 const float* __restrict__ bias,
                                                 float* __restrict__ C,
                                                 int M, int N) {
    __shared__ float As[3][128][36];
    __shared__ float Bs[3][64][36];

    const int tid  = threadIdx.x;
    const int lane = tid & 31;
    const int w    = tid >> 5;
    const int wm   = (w & 3) * 32;
    const int wn   = (w >> 2) * 32;
    const int m0   = blockIdx.x * 128;
    const int n0   = blockIdx.y * 64;

    const int lrow = tid >> 3;         // 0..31
    const int lcol = (tid & 7) * 4;    // 0,4,...,28

    const int niter = K / 32;

    auto issue_tile = [&](int it, int s) {
        int k0 = it * 32;
#pragma unroll
        for (int p = 0; p < 4; p++) {          // A: 128 rows x 32 cols
            int r  = p * 32 + lrow;
            int gm = m0 + r;
            const float* src = A + (size_t)gm * K + k0 + lcol;
            uint32_t dst = smem_u32(&As[s][r][lcol]);
            int sz = (gm < M) ? 16 : 0;        // zero-fill OOB rows
            asm volatile("cp.async.cg.shared.global [%0], [%1], 16, %2;"
                         :: "r"(dst), "l"(src), "r"(sz));
        }
#pragma unroll
        for (int p = 0; p < 2; p++) {          // B: 64 rows x 32 cols
            int r = p * 32 + lrow;
            const float* src = B + (size_t)(n0 + r) * K + k0 + lcol;
            uint32_t dst = smem_u32(&Bs[s][r][lcol]);
            asm volatile("cp.async.cg.shared.global [%0], [%1], 16;"
                         :: "r"(dst), "l"(src));
        }
    };

    float acc[2][4][4];
#pragma unroll
    for (int mt = 0; mt < 2; mt++)
#pragma unroll
        for (int nt = 0; nt < 4; nt++)
#pragma unroll
            for (int j = 0; j < 4; j++) acc[mt][nt][j] = 0.f;

    // Prologue: tiles 0 and 1 in flight
    issue_tile(0, 0);
    asm volatile("cp.async.commit_group;");
    if (niter > 1) issue_tile(1, 1);
    asm volatile("cp.async.commit_group;");

    int s = 0, s2 = 2;   // compute stage, refill stage
    for (int i = 0; i < niter; i++) {
        asm volatile("cp.async.wait_group 1;");   // tile i resident
        __syncthreads();                          // stage s2 fully consumed

        if (i + 2 < niter) issue_tile(i + 2, s2);
        asm volatile("cp.async.commit_group;");

#pragma unroll
        for (int ks = 0; ks < 32; ks += 8) {
            uint32_t af[2][4];
#pragma unroll
            for (int mt = 0; mt < 2; mt++) {
                int r = wm + mt * 16 + (lane >> 2);
                int c = ks + (lane & 3);
                if (CVT_A) {
                    af[mt][0] = to_tf32(As[s][r][c]);
                    af[mt][1] = to_tf32(As[s][r + 8][c]);
                    af[mt][2] = to_tf32(As[s][r][c + 4]);
                    af[mt][3] = to_tf32(As[s][r + 8][c + 4]);
                } else {
                    af[mt][0] = __float_as_uint(As[s][r][c]);
                    af[mt][1] = __float_as_uint(As[s][r + 8][c]);
                    af[mt][2] = __float_as_uint(As[s][r][c + 4]);
                    af[mt][3] = __float_as_uint(As[s][r + 8][c + 4]);
                }
            }
#pragma unroll
            for (int nt = 0; nt < 4; nt++) {
                int cn = wn + nt * 8 + (lane >> 2);
                int ck = ks + (lane & 3);
                uint32_t b0 = __float_as_uint(Bs[s][cn][ck]);
                uint32_t b1 = __float_as_uint(Bs[s][cn][ck + 4]);
                MMA_TF32(acc[0][nt], af[0], b0, b1);
                MMA_TF32(acc[1][nt], af[1], b0, b1);
            }
        }
        s  = (s  == 2) ? 0 : s  + 1;
        s2 = (s2 == 2) ? 0 : s2 + 1;
    }

    // Epilogue
#pragma unroll
    for (int mt = 0; mt < 2; mt++) {
#pragma unroll
        for (int nt = 0; nt < 4; nt++) {
            int row = m0 + wm + mt * 16 + (lane >> 2);
            int col = n0 + wn + nt * 8 + 2 * (lane & 3);
            float b0v = bias[col];
            float b1v = bias[col + 1];
            float v0 = acc[mt][nt][0] + b0v;
            float v1 = acc[mt][nt][1] + b1v;
            float v2 = acc[mt][nt][2] + b0v;
            float v3 = acc[mt][nt][3] + b1v;
            if (RELU) {
                v0 = fmaxf(v0, 0.f); v1 = fmaxf(v1, 0.f);
                v2 = fmaxf(v2, 0.f); v3 = fmaxf(v3, 0.f);
            }
            if (CVT_OUT) {
                v0 = __uint_as_float(to_tf32(v0));
                v1 = __uint_as_float(to_tf32(v1));
                v2 = __uint_as_float(to_tf32(v2));
                v3 = __uint_as_float(to_tf32(v3));
            }
            if (row < M)
                *(float2*)(C + (size_t)row * N + col) = make_float2(v0, v1);
            if (row + 8 < M)
                *(float2*)(C + (size_t)(row + 8) * N + col) = make_float2(v2, v3);
        }
    }
}

// ---------------------------------------------------------------------------
// GRU gate epilogue, vectorized: each thread does 4 consecutive cols.
// ---------------------------------------------------------------------------
__global__ void gates_kernel(const float* __restrict__ x,
                             const float* __restrict__ gi,
                             const float* __restrict__ gh,
                             float* __restrict__ out) {
    int i = blockIdx.x * blockDim.x + threadIdx.x;   // NN*16 work items
    if (i >= NN * 16) return;
    int m = i >> 4;
    int c = (i & 15) * 4;
    const float* gim = gi + (size_t)m * G3;
    const float* ghm = gh + (size_t)m * G3;
    float4 ir  = *(const float4*)(gim + c);
    float4 iz  = *(const float4*)(gim + 64 + c);
    float4 in_ = *(const float4*)(gim + 128 + c);
    float4 hr  = *(const float4*)(ghm + c);
    float4 hz  = *(const float4*)(ghm + 64 + c);
    float4 hn  = *(const float4*)(ghm + 128 + c);
    float4 hv  = *(const float4*)(x + (size_t)m * DI + c);
    float4 o;
    {
        float r = 1.f / (1.f + expf(-(ir.x + hr.x)));
        float z = 1.f / (1.f + expf(-(iz.x + hz.x)));
        float n = tanhf(in_.x + r * hn.x);
        o.x = (1.f - z) * n + z * hv.x;
    }
    {
        float r = 1.f / (1.f + expf(-(ir.y + hr.y)));
        float z = 1.f / (1.f + expf(-(iz.y + hz.y)));
        float n = tanhf(in_.y + r * hn.y);
        o.y = (1.f - z) * n + z * hv.y;
    }
    {
        float r = 1.f / (1.f + expf(-(ir.z + hr.z)));
        float z = 1.f / (1.f + expf(-(iz.z + hz.z)));
        float n = tanhf(in_.z + r * hn.z);
        o.z = (1.f - z) * n + z * hv.z;
    }
    {
        float r = 1.f / (1.f + expf(-(ir.w + hr.w)));
        float z = 1.f / (1.f + expf(-(iz.w + hz.w)));
        float n = tanhf(in_.w + r * hn.w);
        o.w = (1.f - z) * n + z * hv.w;
    }
    *(float4*)(out + (size_t)m * DI + c) = o;
}

// ---------------------------------------------------------------------------
// Launch
// ---------------------------------------------------------------------------
extern "C" void kernel_launch(void* const* d_in, const int* in_sizes, int n_in,
                              void* d_out, int out_size) {
    const float* x     = (const float*)d_in[0];      // [NN, 64]
    const void*  eidx  = d_in[1];                    // [2, NE] int32 or int64
    const void*  etype = d_in[2];                    // [NE]
    const float* ew    = (const float*)d_in[3];      // [NE]
    const float* mlpW  = (const float*)d_in[4];      // [256, 256]
    const float* mlpb  = (const float*)d_in[5];      // [256]
    const float* wih   = (const float*)d_in[6];      // [192, 256]
    const float* whh   = (const float*)d_in[7];      // [192, 64]
    const float* bih   = (const float*)d_in[8];      // [192]
    const float* bhh   = (const float*)d_in[9];      // [192]
    float*       out   = (float*)d_out;              // [NN, 64]

    float *upd, *hid, *gi, *gh, *wbuf;
    cudaGetSymbolAddress((void**)&upd, g_update);
    cudaGetSymbolAddress((void**)&hid, g_hidden);
    cudaGetSymbolAddress((void**)&gi,  g_gi);
    cudaGetSymbolAddress((void**)&gh,  g_gh);
    cudaGetSymbolAddress((void**)&wbuf, g_wbuf);

    const int MB128 = (NN + 127) / 128;   // 782

    // 0) dtype probe + index normalization + weight pre-rounding
    flag_reset_kernel<<<1, 1>>>();
    probe_kernel<<<16, 256>>>((const long long*)eidx);
    convert_kernel<<<(NE + 255) / 256, 256>>>(eidx, etype);
    round_weights_kernel<<<WTOTAL / 256, 256>>>(mlpW, wih, whh);

    // 1) zero accumulator
    zero_kernel<<<25000, 256>>>((float4*)upd, 6400000);

    // 2) edge scatter (vectorized L2 reductions)
    scatter_kernel<<<(NE * 16) / 256, 256>>>(x, ew, upd);

    // 3) hidden = relu(update @ mlpW^T + mlpb), output rounded to tf32
    gemm_tf32<KU, 1, 1, 1><<<dim3(MB128, DH / 64), 256>>>(
        upd, wbuf + WOFF_MLP, mlpb, hid, NN, DH);

    // 4) gi = hidden @ w_ih^T + b_ih   (A already tf32 -> no cvt in loop)
    gemm_tf32<DH, 0, 0, 0><<<dim3(MB128, G3 / 64), 256>>>(
        hid, wbuf + WOFF_IH, bih, gi, NN, G3);

    // 5) gh = x @ w_hh^T + b_hh        (A raw fp32 -> cvt)
    gemm_tf32<DI, 0, 1, 0><<<dim3(MB128, G3 / 64), 256>>>(
        x, wbuf + WOFF_HH, bhh, gh, NN, G3);

    // 6) GRU gates -> out (vectorized)
    gates_kernel<<<(NN * 16 + 255) / 256, 256>>>(x, gi, gh, out);
}

// round 11
// speedup vs baseline: 1.3318x; 1.0216x over previous
#include <cuda_runtime.h>
#include <cuda_bf16.h>
#include <math.h>
#include <stdint.h>

// Problem constants (shapes fixed by the dataset)
#define NN 100000           // nodes
#define NE 1000000          // edges
#define ET 4                // edge types
#define DI 64               // input dim
#define DH 256              // hidden dim
#define KU (ET*DI)          // 256 = update row width
#define G3 (3*DI)           // 192 = gate width
#define NSEG (NN*ET)        // 400000 segments
#define CAP 24              // edges per segment capacity (overflow handled)

// Scratch (device globals — allocation-free)
__device__ float g_update[(size_t)NN * KU];   // 102.4 MB
__device__ float g_hidden[(size_t)NN * DH];   // 102.4 MB
__device__ float g_gi[(size_t)NN * G3];       // 76.8 MB (reused as edge lists pre-GEMM2)
__device__ float g_gh[(size_t)NN * G3];       // 76.8 MB (first 1.6MB reused as counts)
__device__ int   g_src[NE];
__device__ int   g_dst[NE];
__device__ int   g_typ[NE];
__device__ int   g_pos[NE];
__device__ int   g_is_i32;                    // 1 => edge arrays are int32

// Pre-rounded (tf32) weight copies
#define WOFF_MLP 0
#define WOFF_IH  (DH*KU)                   // 65536
#define WOFF_HH  (WOFF_IH + G3*DH)         // 114688
#define WTOTAL   (WOFF_HH + G3*DI)         // 126976
__device__ float g_wbuf[WTOTAL];

// ---------------------------------------------------------------------------
// Index-dtype probe (known good)
// ---------------------------------------------------------------------------
__global__ void flag_reset_kernel() { g_is_i32 = 0; }

__global__ void probe_kernel(const long long* __restrict__ eidx) {
    int i = blockIdx.x * blockDim.x + threadIdx.x;   // 4096 probes
    long long v = eidx[i];
    if (v < 0 || v >= (long long)NN) atomicExch(&g_is_i32, 1);
}

__global__ void convert_kernel(const void* __restrict__ eidx,
                               const void* __restrict__ etype) {
    int e = blockIdx.x * blockDim.x + threadIdx.x;
    if (e >= NE) return;
    if (g_is_i32) {
        const int* p = (const int*)eidx;
        g_src[e] = p[e];
        g_dst[e] = p[NE + e];
        g_typ[e] = ((const int*)etype)[e];
    } else {
        const long long* p = (const long long*)eidx;
        g_src[e] = (int)p[e];
        g_dst[e] = (int)p[NE + e];
        g_typ[e] = (int)((const long long*)etype)[e];
    }
}

// ---------------------------------------------------------------------------
// tf32 helpers
// ---------------------------------------------------------------------------
__device__ __forceinline__ uint32_t to_tf32(float v) {
    uint32_t u;
    asm("cvt.rna.tf32.f32 %0, %1;" : "=r"(u) : "f"(v));
    return u;
}

__global__ void round_weights_kernel(const float* __restrict__ mlpW,
                                     const float* __restrict__ wih,
                                     const float* __restrict__ whh) {
    int i = blockIdx.x * blockDim.x + threadIdx.x;
    if (i >= WTOTAL) return;
    float v;
    if (i < WOFF_IH)       v = mlpW[i];
    else if (i < WOFF_HH)  v = wih[i - WOFF_IH];
    else                   v = whh[i - WOFF_HH];
    g_wbuf[i] = __uint_as_float(to_tf32(v));
}

// ---------------------------------------------------------------------------
// Bucketed scatter: build per-(dst,type) edge lists, then gather + plain store.
// ---------------------------------------------------------------------------
__global__ void zero_counts_kernel(int* __restrict__ cnt) {
    int i = blockIdx.x * blockDim.x + threadIdx.x;
    if (i < NSEG) cnt[i] = 0;
}

__global__ void fill_kernel(const float* __restrict__ ew,
                            int* __restrict__ cnt,
                            unsigned long long* __restrict__ list) {
    int e = blockIdx.x * blockDim.x + threadIdx.x;
    if (e >= NE) return;
    int dst = g_dst[e];
    int t   = g_typ[e];
    if ((unsigned)dst >= NN || (unsigned)t >= ET) { g_pos[e] = CAP; return; }
    int slot = dst * ET + t;
    int pos = atomicAdd(&cnt[slot], 1);
    g_pos[e] = pos;
    if (pos < CAP) {
        unsigned long long pk =
            (unsigned long long)(unsigned)g_src[e] |
            ((unsigned long long)__float_as_uint(ew[e]) << 32);
        list[(size_t)slot * CAP + pos] = pk;
    }
}

// 16 threads per segment; each owns one float4 chunk; exclusive -> plain store.
__global__ void gather_kernel(const float* __restrict__ x,
                              const int* __restrict__ cnt,
                              const unsigned long long* __restrict__ list,
                              float* __restrict__ upd) {
    int i = blockIdx.x * blockDim.x + threadIdx.x;   // NSEG*16 work items
    int seg = i >> 4;
    int c   = i & 15;
    if (seg >= NSEG) return;
    int n = cnt[seg];
    if (n > CAP) n = CAP;
    float4 acc = make_float4(0.f, 0.f, 0.f, 0.f);
    const unsigned long long* lp = list + (size_t)seg * CAP;
    for (int j = 0; j < n; j++) {
        unsigned long long pk = lp[j];
        int   src = (int)(unsigned)(pk & 0xffffffffull);
        float w   = __uint_as_float((uint32_t)(pk >> 32));
        if ((unsigned)src < NN) {
            float4 v = *(const float4*)(x + (size_t)src * DI + c * 4);
            acc.x += w * v.x; acc.y += w * v.y;
            acc.z += w * v.z; acc.w += w * v.w;
        }
    }
    *(float4*)(upd + (size_t)seg * DI + c * 4) = acc;
}

// Overflow edges (essentially never taken) — RED after gather's stores.
__global__ void fallback_kernel(const float* __restrict__ x,
                                const float* __restrict__ ew,
                                float* __restrict__ upd) {
    int e = blockIdx.x * blockDim.x + threadIdx.x;
    if (e >= NE) return;
    if (g_pos[e] < CAP) return;
    int src = g_src[e];
    int dst = g_dst[e];
    int t   = g_typ[e];
    if ((unsigned)src >= NN || (unsigned)dst >= NN || (unsigned)t >= ET) return;
    float w = ew[e];
    float* drow = upd + ((size_t)dst * ET + t) * DI;
    for (int c = 0; c < 16; c++) {
        float4 v = *(const float4*)(x + (size_t)src * DI + c * 4);
        asm volatile("red.global.add.v4.f32 [%0], {%1,%2,%3,%4};"
                     :: "l"(drow + c * 4), "f"(w * v.x), "f"(w * v.y),
                        "f"(w * v.z), "f"(w * v.w)
                     : "memory");
    }
}

// ---------------------------------------------------------------------------
// TF32 mma
// ---------------------------------------------------------------------------
#define MMA_TF32(d, a, b0, b1)                                                 \
    asm volatile(                                                              \
        "mma.sync.aligned.m16n8k8.row.col.f32.tf32.tf32.f32 "                  \
        "{%0,%1,%2,%3},{%4,%5,%6,%7},{%8,%9},{%0,%1,%2,%3};"                   \
        : "+f"((d)[0]), "+f"((d)[1]), "+f"((d)[2]), "+f"((d)[3])               \
        : "r"((a)[0]), "r"((a)[1]), "r"((a)[2]), "r"((a)[3]),                  \
          "r"(b0), "r"(b1))

__device__ __forceinline__ uint32_t smem_u32(const void* p) {
    return (uint32_t)__cvta_generic_to_shared(p);
}

// ---------------------------------------------------------------------------
// TF32 GEMM, BK=32, 3-stage cp.async pipeline (known good from R10)
// ---------------------------------------------------------------------------
template<int K, int RELU, int CVT_A, int CVT_OUT>
__global__ void __launch_bounds__(256) gemm_tf32(const float* __restrict__ A,
                                                 const float* __restrict__ B,
                                                 const float* __restrict__ bias,
                                                 float* __restrict__ C,
                                                 int M, int N) {
    __shared__ float As[3][128][36];
    __shared__ float Bs[3][64][36];

    const int tid  = threadIdx.x;
    const int lane = tid & 31;
    const int w    = tid >> 5;
    const int wm   = (w & 3) * 32;
    const int wn   = (w >> 2) * 32;
    const int m0   = blockIdx.x * 128;
    const int n0   = blockIdx.y * 64;

    const int lrow = tid >> 3;         // 0..31
    const int lcol = (tid & 7) * 4;    // 0,4,...,28

    const int niter = K / 32;

    auto issue_tile = [&](int it, int s) {
        int k0 = it * 32;
#pragma unroll
        for (int p = 0; p < 4; p++) {
            int r  = p * 32 + lrow;
            int gm = m0 + r;
            const float* src = A + (size_t)gm * K + k0 + lcol;
            uint32_t dst = smem_u32(&As[s][r][lcol]);
            int sz = (gm < M) ? 16 : 0;
            asm volatile("cp.async.cg.shared.global [%0], [%1], 16, %2;"
                         :: "r"(dst), "l"(src), "r"(sz));
        }
#pragma unroll
        for (int p = 0; p < 2; p++) {
            int r = p * 32 + lrow;
            const float* src = B + (size_t)(n0 + r) * K + k0 + lcol;
            uint32_t dst = smem_u32(&Bs[s][r][lcol]);
            asm volatile("cp.async.cg.shared.global [%0], [%1], 16;"
                         :: "r"(dst), "l"(src));
        }
    };

    float acc[2][4][4];
#pragma unroll
    for (int mt = 0; mt < 2; mt++)
#pragma unroll
        for (int nt = 0; nt < 4; nt++)
#pragma unroll
            for (int j = 0; j < 4; j++) acc[mt][nt][j] = 0.f;

    issue_tile(0, 0);
    asm volatile("cp.async.commit_group;");
    if (niter > 1) issue_tile(1, 1);
    asm volatile("cp.async.commit_group;");

    int s = 0, s2 = 2;
    for (int i = 0; i < niter; i++) {
        asm volatile("cp.async.wait_group 1;");
        __syncthreads();

        if (i + 2 < niter) issue_tile(i + 2, s2);
        asm volatile("cp.async.commit_group;");

#pragma unroll
        for (int ks = 0; ks < 32; ks += 8) {
            uint32_t af[2][4];
#pragma unroll
            for (int mt = 0; mt < 2; mt++) {
                int r = wm + mt * 16 + (lane >> 2);
                int c = ks + (lane & 3);
                if (CVT_A) {
                    af[mt][0] = to_tf32(As[s][r][c]);
                    af[mt][1] = to_tf32(As[s][r + 8][c]);
                    af[mt][2] = to_tf32(As[s][r][c + 4]);
                    af[mt][3] = to_tf32(As[s][r + 8][c + 4]);
                } else {
                    af[mt][0] = __float_as_uint(As[s][r][c]);
                    af[mt][1] = __float_as_uint(As[s][r + 8][c]);
                    af[mt][2] = __float_as_uint(As[s][r][c + 4]);
                    af[mt][3] = __float_as_uint(As[s][r + 8][c + 4]);
                }
            }
#pragma unroll
            for (int nt = 0; nt < 4; nt++) {
                int cn = wn + nt * 8 + (lane >> 2);
                int ck = ks + (lane & 3);
                uint32_t b0 = __float_as_uint(Bs[s][cn][ck]);
                uint32_t b1 = __float_as_uint(Bs[s][cn][ck + 4]);
                MMA_TF32(acc[0][nt], af[0], b0, b1);
                MMA_TF32(acc[1][nt], af[1], b0, b1);
            }
        }
        s  = (s  == 2) ? 0 : s  + 1;
        s2 = (s2 == 2) ? 0 : s2 + 1;
    }

#pragma unroll
    for (int mt = 0; mt < 2; mt++) {
#pragma unroll
        for (int nt = 0; nt < 4; nt++) {
            int row = m0 + wm + mt * 16 + (lane >> 2);
            int col = n0 + wn + nt * 8 + 2 * (lane & 3);
            float b0v = bias[col];
            float b1v = bias[col + 1];
            float v0 = acc[mt][nt][0] + b0v;
            float v1 = acc[mt][nt][1] + b1v;
            float v2 = acc[mt][nt][2] + b0v;
            float v3 = acc[mt][nt][3] + b1v;
            if (RELU) {
                v0 = fmaxf(v0, 0.f); v1 = fmaxf(v1, 0.f);
                v2 = fmaxf(v2, 0.f); v3 = fmaxf(v3, 0.f);
            }
            if (CVT_OUT) {
                v0 = __uint_as_float(to_tf32(v0));
                v1 = __uint_as_float(to_tf32(v1));
                v2 = __uint_as_float(to_tf32(v2));
                v3 = __uint_as_float(to_tf32(v3));
            }
            if (row < M)
                *(float2*)(C + (size_t)row * N + col) = make_float2(v0, v1);
            if (row + 8 < M)
                *(float2*)(C + (size_t)(row + 8) * N + col) = make_float2(v2, v3);
        }
    }
}

// ---------------------------------------------------------------------------
// GRU gate epilogue, vectorized (known good)
// ---------------------------------------------------------------------------
__global__ void gates_kernel(const float* __restrict__ x,
                             const float* __restrict__ gi,
                             const float* __restrict__ gh,
                             float* __restrict__ out) {
    int i = blockIdx.x * blockDim.x + threadIdx.x;   // NN*16 work items
    if (i >= NN * 16) return;
    int m = i >> 4;
    int c = (i & 15) * 4;
    const float* gim = gi + (size_t)m * G3;
    const float* ghm = gh + (size_t)m * G3;
    float4 ir  = *(const float4*)(gim + c);
    float4 iz  = *(const float4*)(gim + 64 + c);
    float4 in_ = *(const float4*)(gim + 128 + c);
    float4 hr  = *(const float4*)(ghm + c);
    float4 hz  = *(const float4*)(ghm + 64 + c);
    float4 hn  = *(const float4*)(ghm + 128 + c);
    float4 hv  = *(const float4*)(x + (size_t)m * DI + c);
    float4 o;
    {
        float r = 1.f / (1.f + expf(-(ir.x + hr.x)));
        float z = 1.f / (1.f + expf(-(iz.x + hz.x)));
        float n = tanhf(in_.x + r * hn.x);
        o.x = (1.f - z) * n + z * hv.x;
    }
    {
        float r = 1.f / (1.f + expf(-(ir.y + hr.y)));
        float z = 1.f / (1.f + expf(-(iz.y + hz.y)));
        float n = tanhf(in_.y + r * hn.y);
        o.y = (1.f - z) * n + z * hv.y;
    }
    {
        float r = 1.f / (1.f + expf(-(ir.z + hr.z)));
        float z = 1.f / (1.f + expf(-(iz.z + hz.z)));
        float n = tanhf(in_.z + r * hn.z);
        o.z = (1.f - z) * n + z * hv.z;
    }
    {
        float r = 1.f / (1.f + expf(-(ir.w + hr.w)));
        float z = 1.f / (1.f + expf(-(iz.w + hz.w)));
        float n = tanhf(in_.w + r * hn.w);
        o.w = (1.f - z) * n + z * hv.w;
    }
    *(float4*)(out + (size_t)m * DI + c) = o;
}

// ---------------------------------------------------------------------------
// Launch
// ---------------------------------------------------------------------------
extern "C" void kernel_launch(void* const* d_in, const int* in_sizes, int n_in,
                              void* d_out, int out_size) {
    const float* x     = (const float*)d_in[0];      // [NN, 64]
    const void*  eidx  = d_in[1];                    // [2, NE] int32 or int64
    const void*  etype = d_in[2];                    // [NE]
    const float* ew    = (const float*)d_in[3];      // [NE]
    const float* mlpW  = (const float*)d_in[4];      // [256, 256]
    const float* mlpb  = (const float*)d_in[5];      // [256]
    const float* wih   = (const float*)d_in[6];      // [192, 256]
    const float* whh   = (const float*)d_in[7];      // [192, 64]
    const float* bih   = (const float*)d_in[8];      // [192]
    const float* bhh   = (const float*)d_in[9];      // [192]
    float*       out   = (float*)d_out;              // [NN, 64]

    float *upd, *hid, *gi, *gh, *wbuf;
    cudaGetSymbolAddress((void**)&upd, g_update);
    cudaGetSymbolAddress((void**)&hid, g_hidden);
    cudaGetSymbolAddress((void**)&gi,  g_gi);
    cudaGetSymbolAddress((void**)&gh,  g_gh);
    cudaGetSymbolAddress((void**)&wbuf, g_wbuf);

    int* cnt = (int*)gh;                              // 1.6MB of g_gh (pre-GEMM3)
    unsigned long long* list = (unsigned long long*)gi; // 76.8MB of g_gi (pre-GEMM2)

    const int MB128 = (NN + 127) / 128;   // 782

    // 0) dtype probe + index normalization + weight pre-rounding
    flag_reset_kernel<<<1, 1>>>();
    probe_kernel<<<16, 256>>>((const long long*)eidx);
    convert_kernel<<<(NE + 255) / 256, 256>>>(eidx, etype);
    round_weights_kernel<<<WTOTAL / 256, 256>>>(mlpW, wih, whh);

    // 1) bucketed scatter: counts -> lists -> gather (plain stores) -> overflow
    zero_counts_kernel<<<(NSEG + 255) / 256, 256>>>(cnt);
    fill_kernel<<<(NE + 255) / 256, 256>>>(ew, cnt, list);
    gather_kernel<<<(NSEG * 16 + 255) / 256, 256>>>(x, cnt, list, upd);
    fallback_kernel<<<(NE + 255) / 256, 256>>>(x, ew, upd);

    // 2) hidden = relu(update @ mlpW^T + mlpb), output rounded to tf32
    gemm_tf32<KU, 1, 1, 1><<<dim3(MB128, DH / 64), 256>>>(
        upd, wbuf + WOFF_MLP, mlpb, hid, NN, DH);

    // 3) gi = hidden @ w_ih^T + b_ih   (A already tf32 -> no cvt in loop)
    gemm_tf32<DH, 0, 0, 0><<<dim3(MB128, G3 / 64), 256>>>(
        hid, wbuf + WOFF_IH, bih, gi, NN, G3);

    // 4) gh = x @ w_hh^T + b_hh        (A raw fp32 -> cvt)
    gemm_tf32<DI, 0, 1, 0><<<dim3(MB128, G3 / 64), 256>>>(
        x, wbuf + WOFF_HH, bhh, gh, NN, G3);

    // 5) GRU gates -> out (vectorized)
    gates_kernel<<<(NN * 16 + 255) / 256, 256>>>(x, gi, gh, out);
}

// round 13
// speedup vs baseline: 1.3791x; 1.0355x over previous
#include <cuda_runtime.h>
#include <cuda_bf16.h>
#include <math.h>
#include <stdint.h>

// Problem constants (shapes fixed by the dataset)
#define NN 100000           // nodes
#define NE 1000000          // edges
#define ET 4                // edge types
#define DI 64               // input dim
#define DH 256              // hidden dim
#define KU (ET*DI)          // 256 = update row width
#define G3 (3*DI)           // 192 = gate width
#define NSEG (NN*ET)        // 400000 segments
#define CAP 16              // edges per segment capacity (one 128B line; overflow handled)

// Scratch (device globals — allocation-free)
__device__ float g_update[(size_t)NN * KU];   // 102.4 MB
__device__ float g_hidden[(size_t)NN * DH];   // 102.4 MB
__device__ float g_gi[(size_t)NN * G3];       // 76.8 MB (edge lists pre-GEMM2: 400k*16*8B = 51.2MB)
__device__ float g_gh[(size_t)NN * G3];       // 76.8 MB (first 1.6MB = counts)
__device__ int   g_src[NE];
__device__ int   g_dst[NE];
__device__ int   g_typ[NE];
__device__ int   g_pos[NE];
__device__ int   g_is_i32;                    // 1 => edge arrays are int32

// Pre-rounded (tf32) weight copies
#define WOFF_MLP 0
#define WOFF_IH  (DH*KU)                   // 65536
#define WOFF_HH  (WOFF_IH + G3*DH)         // 114688
#define WTOTAL   (WOFF_HH + G3*DI)         // 126976
__device__ float g_wbuf[WTOTAL];

// ---------------------------------------------------------------------------
// tf32 helpers
// ---------------------------------------------------------------------------
__device__ __forceinline__ uint32_t to_tf32(float v) {
    uint32_t u;
    asm("cvt.rna.tf32.f32 %0, %1;" : "=r"(u) : "f"(v));
    return u;
}

__device__ __forceinline__ uint32_t smem_u32(const void* p) {
    return (uint32_t)__cvta_generic_to_shared(p);
}

// ---------------------------------------------------------------------------
// Index-dtype probe + normalization (cnt zeroing fused into convert)
// ---------------------------------------------------------------------------
__global__ void flag_reset_kernel() { g_is_i32 = 0; }

__global__ void probe_kernel(const long long* __restrict__ eidx) {
    int i = blockIdx.x * blockDim.x + threadIdx.x;   // 4096 probes
    long long v = eidx[i];
    if (v < 0 || v >= (long long)NN) atomicExch(&g_is_i32, 1);
}

__global__ void convert_kernel(const void* __restrict__ eidx,
                               const void* __restrict__ etype,
                               int* __restrict__ cnt) {
    int e = blockIdx.x * blockDim.x + threadIdx.x;
    if (e >= NE) return;
    if (e < NSEG) cnt[e] = 0;
    if (g_is_i32) {
        const int* p = (const int*)eidx;
        g_src[e] = p[e];
        g_dst[e] = p[NE + e];
        g_typ[e] = ((const int*)etype)[e];
    } else {
        const long long* p = (const long long*)eidx;
        g_src[e] = (int)p[e];
        g_dst[e] = (int)p[NE + e];
        g_typ[e] = (int)((const long long*)etype)[e];
    }
}

// ---------------------------------------------------------------------------
// fill: per-edge (dst,type) bucketing; packed (src, w) 8B entries, CAP/slot.
// (launch slot #4 — profiled by ncu)
// ---------------------------------------------------------------------------
__global__ void fill_kernel(const float* __restrict__ ew,
                            int* __restrict__ cnt,
                            unsigned long long* __restrict__ list) {
    int e = blockIdx.x * blockDim.x + threadIdx.x;
    if (e >= NE) return;
    int dst = g_dst[e];
    int t   = g_typ[e];
    if ((unsigned)dst >= NN || (unsigned)t >= ET) { g_pos[e] = CAP; return; }
    int slot = dst * ET + t;
    int pos = atomicAdd(&cnt[slot], 1);
    g_pos[e] = pos;
    if (pos < CAP) {
        unsigned long long pk =
            (unsigned long long)(unsigned)g_src[e] |
            ((unsigned long long)__float_as_uint(ew[e]) << 32);
        list[(size_t)slot * CAP + pos] = pk;
    }
}

__global__ void round_weights_kernel(const float* __restrict__ mlpW,
                                     const float* __restrict__ wih,
                                     const float* __restrict__ whh) {
    int i = blockIdx.x * blockDim.x + threadIdx.x;
    if (i >= WTOTAL) return;
    float v;
    if (i < WOFF_IH)       v = mlpW[i];
    else if (i < WOFF_HH)  v = wih[i - WOFF_IH];
    else                   v = whh[i - WOFF_HH];
    g_wbuf[i] = __uint_as_float(to_tf32(v));
}

// ---------------------------------------------------------------------------
// gather: 8 threads/segment, each owns 8 consecutive floats (2x float4).
// Exclusive ownership -> plain stores. Output rounded rna->tf32 so GEMM1
// can skip its A-side cvt (identical math to rounding inside the GEMM).
// ---------------------------------------------------------------------------
__global__ void gather_kernel(const float* __restrict__ x,
                              const int* __restrict__ cnt,
                              const unsigned long long* __restrict__ list,
                              float* __restrict__ upd) {
    int i = blockIdx.x * blockDim.x + threadIdx.x;   // NSEG*8 work items
    int seg = i >> 3;
    int c   = (i & 7) * 8;     // float offset within the 64-wide row
    if (seg >= NSEG) return;
    int n = cnt[seg];
    if (n > CAP) n = CAP;
    float4 a0 = make_float4(0.f, 0.f, 0.f, 0.f);
    float4 a1 = make_float4(0.f, 0.f, 0.f, 0.f);
    const unsigned long long* lp = list + (size_t)seg * CAP;
    for (int j = 0; j < n; j++) {
        unsigned long long pk = lp[j];
        int   src = (int)(unsigned)(pk & 0xffffffffull);
        float w   = __uint_as_float((uint32_t)(pk >> 32));
        if ((unsigned)src < NN) {
            const float* xr = x + (size_t)src * DI + c;
            float4 v0 = *(const float4*)(xr);
            float4 v1 = *(const float4*)(xr + 4);
            a0.x += w * v0.x; a0.y += w * v0.y; a0.z += w * v0.z; a0.w += w * v0.w;
            a1.x += w * v1.x; a1.y += w * v1.y; a1.z += w * v1.z; a1.w += w * v1.w;
        }
    }
    a0.x = __uint_as_float(to_tf32(a0.x));
    a0.y = __uint_as_float(to_tf32(a0.y));
    a0.z = __uint_as_float(to_tf32(a0.z));
    a0.w = __uint_as_float(to_tf32(a0.w));
    a1.x = __uint_as_float(to_tf32(a1.x));
    a1.y = __uint_as_float(to_tf32(a1.y));
    a1.z = __uint_as_float(to_tf32(a1.z));
    a1.w = __uint_as_float(to_tf32(a1.w));
    float* ur = upd + (size_t)seg * DI + c;
    *(float4*)(ur)     = a0;
    *(float4*)(ur + 4) = a1;
}

// Overflow edges (essentially never taken with this dataset) — RED after
// gather's stores. NOTE: fp32 adds here are not tf32-rounded; GEMM1 with
// CVT_A=0 would consume raw bits, so fallback rounds its addend to tf32 first
// (sum-of-tf32 stays representable enough; error bounded by normal path).
__global__ void fallback_kernel(const float* __restrict__ x,
                                const float* __restrict__ ew,
                                float* __restrict__ upd) {
    int e = blockIdx.x * blockDim.x + threadIdx.x;
    if (e >= NE) return;
    if (g_pos[e] < CAP) return;
    int src = g_src[e];
    int dst = g_dst[e];
    int t   = g_typ[e];
    if ((unsigned)src >= NN || (unsigned)dst >= NN || (unsigned)t >= ET) return;
    float w = ew[e];
    float* drow = upd + ((size_t)dst * ET + t) * DI;
    for (int c = 0; c < 16; c++) {
        float4 v = *(const float4*)(x + (size_t)src * DI + c * 4);
        float p0 = __uint_as_float(to_tf32(w * v.x));
        float p1 = __uint_as_float(to_tf32(w * v.y));
        float p2 = __uint_as_float(to_tf32(w * v.z));
        float p3 = __uint_as_float(to_tf32(w * v.w));
        asm volatile("red.global.add.v4.f32 [%0], {%1,%2,%3,%4};"
                     :: "l"(drow + c * 4), "f"(p0), "f"(p1), "f"(p2), "f"(p3)
                     : "memory");
    }
}

// ---------------------------------------------------------------------------
// TF32 mma.sync GEMM, BK=32, 3-stage cp.async (known good from R10/R11)
// ---------------------------------------------------------------------------
#define MMA_TF32(d, a, b0, b1)                                                 \
    asm volatile(                                                              \
        "mma.sync.aligned.m16n8k8.row.col.f32.tf32.tf32.f32 "                  \
        "{%0,%1,%2,%3},{%4,%5,%6,%7},{%8,%9},{%0,%1,%2,%3};"                   \
        : "+f"((d)[0]), "+f"((d)[1]), "+f"((d)[2]), "+f"((d)[3])               \
        : "r"((a)[0]), "r"((a)[1]), "r"((a)[2]), "r"((a)[3]),                  \
          "r"(b0), "r"(b1))

template<int K, int RELU, int CVT_A, int CVT_OUT>
__global__ void __launch_bounds__(256) gemm_tf32(const float* __restrict__ A,
                                                 const float* __restrict__ B,
                                                 const float* __restrict__ bias,
                                                 float* __restrict__ C,
                                                 int M, int N) {
    __shared__ float As[3][128][36];
    __shared__ float Bs[3][64][36];

    const int tid  = threadIdx.x;
    const int lane = tid & 31;
    const int w    = tid >> 5;
    const int wm   = (w & 3) * 32;
    const int wn   = (w >> 2) * 32;
    const int m0   = blockIdx.x * 128;
    const int n0   = blockIdx.y * 64;

    const int lrow = tid >> 3;
    const int lcol = (tid & 7) * 4;

    const int niter = K / 32;

    auto issue_tile = [&](int it, int s) {
        int k0 = it * 32;
#pragma unroll
        for (int p = 0; p < 4; p++) {
            int r  = p * 32 + lrow;
            int gm = m0 + r;
            const float* src = A + (size_t)gm * K + k0 + lcol;
            uint32_t dst = smem_u32(&As[s][r][lcol]);
            int sz = (gm < M) ? 16 : 0;
            asm volatile("cp.async.cg.shared.global [%0], [%1], 16, %2;"
                         :: "r"(dst), "l"(src), "r"(sz));
        }
#pragma unroll
        for (int p = 0; p < 2; p++) {
            int r = p * 32 + lrow;
            const float* src = B + (size_t)(n0 + r) * K + k0 + lcol;
            uint32_t dst = smem_u32(&Bs[s][r][lcol]);
            asm volatile("cp.async.cg.shared.global [%0], [%1], 16;"
                         :: "r"(dst), "l"(src));
        }
    };

    float acc[2][4][4];
#pragma unroll
    for (int mt = 0; mt < 2; mt++)
#pragma unroll
        for (int nt = 0; nt < 4; nt++)
#pragma unroll
            for (int j = 0; j < 4; j++) acc[mt][nt][j] = 0.f;

    issue_tile(0, 0);
    asm volatile("cp.async.commit_group;");
    if (niter > 1) issue_tile(1, 1);
    asm volatile("cp.async.commit_group;");

    int s = 0, s2 = 2;
    for (int i = 0; i < niter; i++) {
        asm volatile("cp.async.wait_group 1;");
        __syncthreads();

        if (i + 2 < niter) issue_tile(i + 2, s2);
        asm volatile("cp.async.commit_group;");

#pragma unroll
        for (int ks = 0; ks < 32; ks += 8) {
            uint32_t af[2][4];
#pragma unroll
            for (int mt = 0; mt < 2; mt++) {
                int r = wm + mt * 16 + (lane >> 2);
                int c = ks + (lane & 3);
                if (CVT_A) {
                    af[mt][0] = to_tf32(As[s][r][c]);
                    af[mt][1] = to_tf32(As[s][r + 8][c]);
                    af[mt][2] = to_tf32(As[s][r][c + 4]);
                    af[mt][3] = to_tf32(As[s][r + 8][c + 4]);
                } else {
                    af[mt][0] = __float_as_uint(As[s][r][c]);
                    af[mt][1] = __float_as_uint(As[s][r + 8][c]);
                    af[mt][2] = __float_as_uint(As[s][r][c + 4]);
                    af[mt][3] = __float_as_uint(As[s][r + 8][c + 4]);
                }
            }
#pragma unroll
            for (int nt = 0; nt < 4; nt++) {
                int cn = wn + nt * 8 + (lane >> 2);
                int ck = ks + (lane & 3);
                uint32_t b0 = __float_as_uint(Bs[s][cn][ck]);
                uint32_t b1 = __float_as_uint(Bs[s][cn][ck + 4]);
                MMA_TF32(acc[0][nt], af[0], b0, b1);
                MMA_TF32(acc[1][nt], af[1], b0, b1);
            }
        }
        s  = (s  == 2) ? 0 : s  + 1;
        s2 = (s2 == 2) ? 0 : s2 + 1;
    }

#pragma unroll
    for (int mt = 0; mt < 2; mt++) {
#pragma unroll
        for (int nt = 0; nt < 4; nt++) {
            int row = m0 + wm + mt * 16 + (lane >> 2);
            int col = n0 + wn + nt * 8 + 2 * (lane & 3);
            float b0v = bias[col];
            float b1v = bias[col + 1];
            float v0 = acc[mt][nt][0] + b0v;
            float v1 = acc[mt][nt][1] + b1v;
            float v2 = acc[mt][nt][2] + b0v;
            float v3 = acc[mt][nt][3] + b1v;
            if (RELU) {
                v0 = fmaxf(v0, 0.f); v1 = fmaxf(v1, 0.f);
                v2 = fmaxf(v2, 0.f); v3 = fmaxf(v3, 0.f);
            }
            if (CVT_OUT) {
                v0 = __uint_as_float(to_tf32(v0));
                v1 = __uint_as_float(to_tf32(v1));
                v2 = __uint_as_float(to_tf32(v2));
                v3 = __uint_as_float(to_tf32(v3));
            }
            if (row < M)
                *(float2*)(C + (size_t)row * N + col) = make_float2(v0, v1);
            if (row + 8 < M)
                *(float2*)(C + (size_t)(row + 8) * N + col) = make_float2(v2, v3);
        }
    }
}

// ---------------------------------------------------------------------------
// GRU gate epilogue, vectorized (known good)
// ---------------------------------------------------------------------------
__global__ void gates_kernel(const float* __restrict__ x,
                             const float* __restrict__ gi,
                             const float* __restrict__ gh,
                             float* __restrict__ out) {
    int i = blockIdx.x * blockDim.x + threadIdx.x;   // NN*16 work items
    if (i >= NN * 16) return;
    int m = i >> 4;
    int c = (i & 15) * 4;
    const float* gim = gi + (size_t)m * G3;
    const float* ghm = gh + (size_t)m * G3;
    float4 ir  = *(const float4*)(gim + c);
    float4 iz  = *(const float4*)(gim + 64 + c);
    float4 in_ = *(const float4*)(gim + 128 + c);
    float4 hr  = *(const float4*)(ghm + c);
    float4 hz  = *(const float4*)(ghm + 64 + c);
    float4 hn  = *(const float4*)(ghm + 128 + c);
    float4 hv  = *(const float4*)(x + (size_t)m * DI + c);
    float4 o;
    {
        float r = 1.f / (1.f + expf(-(ir.x + hr.x)));
        float z = 1.f / (1.f + expf(-(iz.x + hz.x)));
        float n = tanhf(in_.x + r * hn.x);
        o.x = (1.f - z) * n + z * hv.x;
    }
    {
        float r = 1.f / (1.f + expf(-(ir.y + hr.y)));
        float z = 1.f / (1.f + expf(-(iz.y + hz.y)));
        float n = tanhf(in_.y + r * hn.y);
        o.y = (1.f - z) * n + z * hv.y;
    }
    {
        float r = 1.f / (1.f + expf(-(ir.z + hr.z)));
        float z = 1.f / (1.f + expf(-(iz.z + hz.z)));
        float n = tanhf(in_.z + r * hn.z);
        o.z = (1.f - z) * n + z * hv.z;
    }
    {
        float r = 1.f / (1.f + expf(-(ir.w + hr.w)));
        float z = 1.f / (1.f + expf(-(iz.w + hz.w)));
        float n = tanhf(in_.w + r * hn.w);
        o.w = (1.f - z) * n + z * hv.w;
    }
    *(float4*)(out + (size_t)m * DI + c) = o;
}

// ---------------------------------------------------------------------------
// Launch
// ---------------------------------------------------------------------------
extern "C" void kernel_launch(void* const* d_in, const int* in_sizes, int n_in,
                              void* d_out, int out_size) {
    const float* x     = (const float*)d_in[0];      // [NN, 64]
    const void*  eidx  = d_in[1];                    // [2, NE] int32 or int64
    const void*  etype = d_in[2];                    // [NE]
    const float* ew    = (const float*)d_in[3];      // [NE]
    const float* mlpW  = (const float*)d_in[4];      // [256, 256]
    const float* mlpb  = (const float*)d_in[5];      // [256]
    const float* wih   = (const float*)d_in[6];      // [192, 256]
    const float* whh   = (const float*)d_in[7];      // [192, 64]
    const float* bih   = (const float*)d_in[8];      // [192]
    const float* bhh   = (const float*)d_in[9];      // [192]
    float*       out   = (float*)d_out;              // [NN, 64]

    float *upd, *hid, *gi, *gh, *wbuf;
    cudaGetSymbolAddress((void**)&upd, g_update);
    cudaGetSymbolAddress((void**)&hid, g_hidden);
    cudaGetSymbolAddress((void**)&gi,  g_gi);
    cudaGetSymbolAddress((void**)&gh,  g_gh);
    cudaGetSymbolAddress((void**)&wbuf, g_wbuf);

    int* cnt = (int*)gh;                                // 1.6MB of g_gh
    unsigned long long* list = (unsigned long long*)gi; // 51.2MB of g_gi

    const int MB128 = (NN + 127) / 128;   // 782

    // 0) dtype probe + normalization (+cnt zero); fill at profiled slot #4
    flag_reset_kernel<<<1, 1>>>();
    probe_kernel<<<16, 256>>>((const long long*)eidx);
    convert_kernel<<<(NE + 255) / 256, 256>>>(eidx, etype, cnt);
    fill_kernel<<<(NE + 255) / 256, 256>>>(ew, cnt, list);
    round_weights_kernel<<<WTOTAL / 256, 256>>>(mlpW, wih, whh);

    // 1) gather (plain tf32-rounded stores) + overflow fallback
    gather_kernel<<<(NSEG * 8 + 255) / 256, 256>>>(x, cnt, list, upd);
    fallback_kernel<<<(NE + 255) / 256, 256>>>(x, ew, upd);

    // 2) hidden = relu(update @ mlpW^T + mlpb)  — A already tf32 (CVT_A=0)
    gemm_tf32<KU, 1, 0, 1><<<dim3(MB128, DH / 64), 256>>>(
        upd, wbuf + WOFF_MLP, mlpb, hid, NN, DH);

    // 3) gi = hidden @ w_ih^T + b_ih            — A already tf32 (CVT_A=0)
    gemm_tf32<DH, 0, 0, 0><<<dim3(MB128, G3 / 64), 256>>>(
        hid, wbuf + WOFF_IH, bih, gi, NN, G3);

    // 4) gh = x @ w_hh^T + b_hh                 — A raw fp32 (CVT_A=1)
    gemm_tf32<DI, 0, 1, 0><<<dim3(MB128, G3 / 64), 256>>>(
        x, wbuf + WOFF_HH, bhh, gh, NN, G3);

    // 5) GRU gates -> out (vectorized)
    gates_kernel<<<(NN * 16 + 255) / 256, 256>>>(x, gi, gh, out);
}

// round 14
// speedup vs baseline: 1.3994x; 1.0147x over previous
#include <cuda_runtime.h>
#include <cuda_bf16.h>
#include <math.h>
#include <stdint.h>

// Problem constants (shapes fixed by the dataset)
#define NN 100000           // nodes
#define NE 1000000          // edges
#define ET 4                // edge types
#define DI 64               // input dim
#define DH 256              // hidden dim
#define KU (ET*DI)          // 256 = update row width
#define G3 (3*DI)           // 192 = gate width
#define NSEG (NN*ET)        // 400000 segments
#define CAP 16              // edges per segment capacity (one 128B line; overflow handled)

// Scratch (device globals — allocation-free)
__device__ float g_update[(size_t)NN * KU];   // 102.4 MB
__device__ float g_hidden[(size_t)NN * DH];   // 102.4 MB
__device__ float g_gi[(size_t)NN * G3];       // 76.8 MB (edge lists pre-GEMM2: 400k*16*8B = 51.2MB)
__device__ float g_gh[(size_t)NN * G3];       // 76.8 MB (first 1.6MB = counts)
__device__ int   g_src[NE];                   // overflow-only
__device__ int   g_dst[NE];                   // overflow-only
__device__ int   g_typ[NE];                   // overflow-only
__device__ int   g_pos[NE];
__device__ int   g_is_i32;                    // 1 => edge arrays are int32

// Pre-rounded (tf32) weight copies
#define WOFF_MLP 0
#define WOFF_IH  (DH*KU)                   // 65536
#define WOFF_HH  (WOFF_IH + G3*DH)         // 114688
#define WTOTAL   (WOFF_HH + G3*DI)         // 126976
__device__ float g_wbuf[WTOTAL];

// ---------------------------------------------------------------------------
// tf32 helpers
// ---------------------------------------------------------------------------
__device__ __forceinline__ uint32_t to_tf32(float v) {
    uint32_t u;
    asm("cvt.rna.tf32.f32 %0, %1;" : "=r"(u) : "f"(v));
    return u;
}

__device__ __forceinline__ uint32_t smem_u32(const void* p) {
    return (uint32_t)__cvta_generic_to_shared(p);
}

// ---------------------------------------------------------------------------
// init: zero the segment counters + reset the dtype flag
// ---------------------------------------------------------------------------
__global__ void init_kernel(int* __restrict__ cnt) {
    int i = blockIdx.x * blockDim.x + threadIdx.x;
    if (i < NSEG) cnt[i] = 0;
    if (i == 0) g_is_i32 = 0;
}

__global__ void probe_kernel(const long long* __restrict__ eidx) {
    int i = blockIdx.x * blockDim.x + threadIdx.x;   // 4096 probes
    long long v = eidx[i];
    if (v < 0 || v >= (long long)NN) atomicExch(&g_is_i32, 1);
}

// ---------------------------------------------------------------------------
// Fused convert+fill: read raw edge arrays (either dtype), bucket into
// per-(dst,type) lists of packed (src, w) 8B entries. Overflow edges
// (pos >= CAP) record src/dst/typ for the fallback; OOB edges get pos=-1.
// ---------------------------------------------------------------------------
__global__ void fill_kernel(const void* __restrict__ eidx,
                            const void* __restrict__ etype,
                            const float* __restrict__ ew,
                            int* __restrict__ cnt,
                            unsigned long long* __restrict__ list) {
    int e = blockIdx.x * blockDim.x + threadIdx.x;
    if (e >= NE) return;
    int src, dst, t;
    if (g_is_i32) {
        const int* p = (const int*)eidx;
        src = p[e];
        dst = p[NE + e];
        t   = ((const int*)etype)[e];
    } else {
        const long long* p = (const long long*)eidx;
        src = (int)p[e];
        dst = (int)p[NE + e];
        t   = (int)((const long long*)etype)[e];
    }
    if ((unsigned)dst >= NN || (unsigned)t >= ET || (unsigned)src >= NN) {
        g_pos[e] = -1;               // skipped by fallback (pos < CAP)
        return;
    }
    int slot = dst * ET + t;
    int pos = atomicAdd(&cnt[slot], 1);
    g_pos[e] = pos;
    if (pos < CAP) {
        unsigned long long pk =
            (unsigned long long)(unsigned)src |
            ((unsigned long long)__float_as_uint(ew[e]) << 32);
        list[(size_t)slot * CAP + pos] = pk;
    } else {                          // overflow: record for fallback
        g_src[e] = src;
        g_dst[e] = dst;
        g_typ[e] = t;
    }
}

__global__ void round_weights_kernel(const float* __restrict__ mlpW,
                                     const float* __restrict__ wih,
                                     const float* __restrict__ whh) {
    int i = blockIdx.x * blockDim.x + threadIdx.x;
    if (i >= WTOTAL) return;
    float v;
    if (i < WOFF_IH)       v = mlpW[i];
    else if (i < WOFF_HH)  v = wih[i - WOFF_IH];
    else                   v = whh[i - WOFF_HH];
    g_wbuf[i] = __uint_as_float(to_tf32(v));
}

// ---------------------------------------------------------------------------
// gather: 8 threads/segment, each owns 8 consecutive floats (2x float4).
// Exclusive ownership -> plain stores. Output rounded rna->tf32 so GEMM1
// can skip its A-side cvt. (launch slot #4 — profiled by ncu this round)
// ---------------------------------------------------------------------------
__global__ void gather_kernel(const float* __restrict__ x,
                              const int* __restrict__ cnt,
                              const unsigned long long* __restrict__ list,
                              float* __restrict__ upd) {
    int i = blockIdx.x * blockDim.x + threadIdx.x;   // NSEG*8 work items
    int seg = i >> 3;
    int c   = (i & 7) * 8;     // float offset within the 64-wide row
    if (seg >= NSEG) return;
    int n = cnt[seg];
    if (n > CAP) n = CAP;
    float4 a0 = make_float4(0.f, 0.f, 0.f, 0.f);
    float4 a1 = make_float4(0.f, 0.f, 0.f, 0.f);
    const unsigned long long* lp = list + (size_t)seg * CAP;
    for (int j = 0; j < n; j++) {
        unsigned long long pk = lp[j];
        int   src = (int)(unsigned)(pk & 0xffffffffull);
        float w   = __uint_as_float((uint32_t)(pk >> 32));
        if ((unsigned)src < NN) {
            const float* xr = x + (size_t)src * DI + c;
            float4 v0 = *(const float4*)(xr);
            float4 v1 = *(const float4*)(xr + 4);
            a0.x += w * v0.x; a0.y += w * v0.y; a0.z += w * v0.z; a0.w += w * v0.w;
            a1.x += w * v1.x; a1.y += w * v1.y; a1.z += w * v1.z; a1.w += w * v1.w;
        }
    }
    a0.x = __uint_as_float(to_tf32(a0.x));
    a0.y = __uint_as_float(to_tf32(a0.y));
    a0.z = __uint_as_float(to_tf32(a0.z));
    a0.w = __uint_as_float(to_tf32(a0.w));
    a1.x = __uint_as_float(to_tf32(a1.x));
    a1.y = __uint_as_float(to_tf32(a1.y));
    a1.z = __uint_as_float(to_tf32(a1.z));
    a1.w = __uint_as_float(to_tf32(a1.w));
    float* ur = upd + (size_t)seg * DI + c;
    *(float4*)(ur)     = a0;
    *(float4*)(ur + 4) = a1;
}

// Overflow edges (essentially never taken) — RED after gather's stores,
// addends pre-rounded to tf32 to match the CVT_A=0 GEMM1 contract.
__global__ void fallback_kernel(const float* __restrict__ x,
                                const float* __restrict__ ew,
                                float* __restrict__ upd) {
    int e = blockIdx.x * blockDim.x + threadIdx.x;
    if (e >= NE) return;
    if (g_pos[e] < CAP) return;
    int src = g_src[e];
    int dst = g_dst[e];
    int t   = g_typ[e];
    if ((unsigned)src >= NN || (unsigned)dst >= NN || (unsigned)t >= ET) return;
    float w = ew[e];
    float* drow = upd + ((size_t)dst * ET + t) * DI;
    for (int c = 0; c < 16; c++) {
        float4 v = *(const float4*)(x + (size_t)src * DI + c * 4);
        float p0 = __uint_as_float(to_tf32(w * v.x));
        float p1 = __uint_as_float(to_tf32(w * v.y));
        float p2 = __uint_as_float(to_tf32(w * v.z));
        float p3 = __uint_as_float(to_tf32(w * v.w));
        asm volatile("red.global.add.v4.f32 [%0], {%1,%2,%3,%4};"
                     :: "l"(drow + c * 4), "f"(p0), "f"(p1), "f"(p2), "f"(p3)
                     : "memory");
    }
}

// ---------------------------------------------------------------------------
// TF32 mma.sync GEMM, BK=32, 3-stage cp.async (known good)
// ---------------------------------------------------------------------------
#define MMA_TF32(d, a, b0, b1)                                                 \
    asm volatile(                                                              \
        "mma.sync.aligned.m16n8k8.row.col.f32.tf32.tf32.f32 "                  \
        "{%0,%1,%2,%3},{%4,%5,%6,%7},{%8,%9},{%0,%1,%2,%3};"                   \
        : "+f"((d)[0]), "+f"((d)[1]), "+f"((d)[2]), "+f"((d)[3])               \
        : "r"((a)[0]), "r"((a)[1]), "r"((a)[2]), "r"((a)[3]),                  \
          "r"(b0), "r"(b1))

template<int K, int RELU, int CVT_A, int CVT_OUT>
__global__ void __launch_bounds__(256) gemm_tf32(const float* __restrict__ A,
                                                 const float* __restrict__ B,
                                                 const float* __restrict__ bias,
                                                 float* __restrict__ C,
                                                 int M, int N) {
    __shared__ float As[3][128][36];
    __shared__ float Bs[3][64][36];

    const int tid  = threadIdx.x;
    const int lane = tid & 31;
    const int w    = tid >> 5;
    const int wm   = (w & 3) * 32;
    const int wn   = (w >> 2) * 32;
    const int m0   = blockIdx.x * 128;
    const int n0   = blockIdx.y * 64;

    const int lrow = tid >> 3;
    const int lcol = (tid & 7) * 4;

    const int niter = K / 32;

    auto issue_tile = [&](int it, int s) {
        int k0 = it * 32;
#pragma unroll
        for (int p = 0; p < 4; p++) {
            int r  = p * 32 + lrow;
            int gm = m0 + r;
            const float* src = A + (size_t)gm * K + k0 + lcol;
            uint32_t dst = smem_u32(&As[s][r][lcol]);
            int sz = (gm < M) ? 16 : 0;
            asm volatile("cp.async.cg.shared.global [%0], [%1], 16, %2;"
                         :: "r"(dst), "l"(src), "r"(sz));
        }
#pragma unroll
        for (int p = 0; p < 2; p++) {
            int r = p * 32 + lrow;
            const float* src = B + (size_t)(n0 + r) * K + k0 + lcol;
            uint32_t dst = smem_u32(&Bs[s][r][lcol]);
            asm volatile("cp.async.cg.shared.global [%0], [%1], 16;"
                         :: "r"(dst), "l"(src));
        }
    };

    float acc[2][4][4];
#pragma unroll
    for (int mt = 0; mt < 2; mt++)
#pragma unroll
        for (int nt = 0; nt < 4; nt++)
#pragma unroll
            for (int j = 0; j < 4; j++) acc[mt][nt][j] = 0.f;

    issue_tile(0, 0);
    asm volatile("cp.async.commit_group;");
    if (niter > 1) issue_tile(1, 1);
    asm volatile("cp.async.commit_group;");

    int s = 0, s2 = 2;
    for (int i = 0; i < niter; i++) {
        asm volatile("cp.async.wait_group 1;");
        __syncthreads();

        if (i + 2 < niter) issue_tile(i + 2, s2);
        asm volatile("cp.async.commit_group;");

#pragma unroll
        for (int ks = 0; ks < 32; ks += 8) {
            uint32_t af[2][4];
#pragma unroll
            for (int mt = 0; mt < 2; mt++) {
                int r = wm + mt * 16 + (lane >> 2);
                int c = ks + (lane & 3);
                if (CVT_A) {
                    af[mt][0] = to_tf32(As[s][r][c]);
                    af[mt][1] = to_tf32(As[s][r + 8][c]);
                    af[mt][2] = to_tf32(As[s][r][c + 4]);
                    af[mt][3] = to_tf32(As[s][r + 8][c + 4]);
                } else {
                    af[mt][0] = __float_as_uint(As[s][r][c]);
                    af[mt][1] = __float_as_uint(As[s][r + 8][c]);
                    af[mt][2] = __float_as_uint(As[s][r][c + 4]);
                    af[mt][3] = __float_as_uint(As[s][r + 8][c + 4]);
                }
            }
#pragma unroll
            for (int nt = 0; nt < 4; nt++) {
                int cn = wn + nt * 8 + (lane >> 2);
                int ck = ks + (lane & 3);
                uint32_t b0 = __float_as_uint(Bs[s][cn][ck]);
                uint32_t b1 = __float_as_uint(Bs[s][cn][ck + 4]);
                MMA_TF32(acc[0][nt], af[0], b0, b1);
                MMA_TF32(acc[1][nt], af[1], b0, b1);
            }
        }
        s  = (s  == 2) ? 0 : s  + 1;
        s2 = (s2 == 2) ? 0 : s2 + 1;
    }

#pragma unroll
    for (int mt = 0; mt < 2; mt++) {
#pragma unroll
        for (int nt = 0; nt < 4; nt++) {
            int row = m0 + wm + mt * 16 + (lane >> 2);
            int col = n0 + wn + nt * 8 + 2 * (lane & 3);
            float b0v = bias[col];
            float b1v = bias[col + 1];
            float v0 = acc[mt][nt][0] + b0v;
            float v1 = acc[mt][nt][1] + b1v;
            float v2 = acc[mt][nt][2] + b0v;
            float v3 = acc[mt][nt][3] + b1v;
            if (RELU) {
                v0 = fmaxf(v0, 0.f); v1 = fmaxf(v1, 0.f);
                v2 = fmaxf(v2, 0.f); v3 = fmaxf(v3, 0.f);
            }
            if (CVT_OUT) {
                v0 = __uint_as_float(to_tf32(v0));
                v1 = __uint_as_float(to_tf32(v1));
                v2 = __uint_as_float(to_tf32(v2));
                v3 = __uint_as_float(to_tf32(v3));
            }
            if (row < M)
                *(float2*)(C + (size_t)row * N + col) = make_float2(v0, v1);
            if (row + 8 < M)
                *(float2*)(C + (size_t)(row + 8) * N + col) = make_float2(v2, v3);
        }
    }
}

// ---------------------------------------------------------------------------
// GRU gate epilogue, vectorized (known good)
// ---------------------------------------------------------------------------
__global__ void gates_kernel(const float* __restrict__ x,
                             const float* __restrict__ gi,
                             const float* __restrict__ gh,
                             float* __restrict__ out) {
    int i = blockIdx.x * blockDim.x + threadIdx.x;   // NN*16 work items
    if (i >= NN * 16) return;
    int m = i >> 4;
    int c = (i & 15) * 4;
    const float* gim = gi + (size_t)m * G3;
    const float* ghm = gh + (size_t)m * G3;
    float4 ir  = *(const float4*)(gim + c);
    float4 iz  = *(const float4*)(gim + 64 + c);
    float4 in_ = *(const float4*)(gim + 128 + c);
    float4 hr  = *(const float4*)(ghm + c);
    float4 hz  = *(const float4*)(ghm + 64 + c);
    float4 hn  = *(const float4*)(ghm + 128 + c);
    float4 hv  = *(const float4*)(x + (size_t)m * DI + c);
    float4 o;
    {
        float r = 1.f / (1.f + expf(-(ir.x + hr.x)));
        float z = 1.f / (1.f + expf(-(iz.x + hz.x)));
        float n = tanhf(in_.x + r * hn.x);
        o.x = (1.f - z) * n + z * hv.x;
    }
    {
        float r = 1.f / (1.f + expf(-(ir.y + hr.y)));
        float z = 1.f / (1.f + expf(-(iz.y + hz.y)));
        float n = tanhf(in_.y + r * hn.y);
        o.y = (1.f - z) * n + z * hv.y;
    }
    {
        float r = 1.f / (1.f + expf(-(ir.z + hr.z)));
        float z = 1.f / (1.f + expf(-(iz.z + hz.z)));
        float n = tanhf(in_.z + r * hn.z);
        o.z = (1.f - z) * n + z * hv.z;
    }
    {
        float r = 1.f / (1.f + expf(-(ir.w + hr.w)));
        float z = 1.f / (1.f + expf(-(iz.w + hz.w)));
        float n = tanhf(in_.w + r * hn.w);
        o.w = (1.f - z) * n + z * hv.w;
    }
    *(float4*)(out + (size_t)m * DI + c) = o;
}

// ---------------------------------------------------------------------------
// Launch
// ---------------------------------------------------------------------------
extern "C" void kernel_launch(void* const* d_in, const int* in_sizes, int n_in,
                              void* d_out, int out_size) {
    const float* x     = (const float*)d_in[0];      // [NN, 64]
    const void*  eidx  = d_in[1];                    // [2, NE] int32 or int64
    const void*  etype = d_in[2];                    // [NE]
    const float* ew    = (const float*)d_in[3];      // [NE]
    const float* mlpW  = (const float*)d_in[4];      // [256, 256]
    const float* mlpb  = (const float*)d_in[5];      // [256]
    const float* wih   = (const float*)d_in[6];      // [192, 256]
    const float* whh   = (const float*)d_in[7];      // [192, 64]
    const float* bih   = (const float*)d_in[8];      // [192]
    const float* bhh   = (const float*)d_in[9];      // [192]
    float*       out   = (float*)d_out;              // [NN, 64]

    float *upd, *hid, *gi, *gh, *wbuf;
    cudaGetSymbolAddress((void**)&upd, g_update);
    cudaGetSymbolAddress((void**)&hid, g_hidden);
    cudaGetSymbolAddress((void**)&gi,  g_gi);
    cudaGetSymbolAddress((void**)&gh,  g_gh);
    cudaGetSymbolAddress((void**)&wbuf, g_wbuf);

    int* cnt = (int*)gh;                                // 1.6MB of g_gh
    unsigned long long* list = (unsigned long long*)gi; // 51.2MB of g_gi

    const int MB128 = (NN + 127) / 128;   // 782

    // 0) init counters+flag, dtype probe, fused bucket-fill
    init_kernel<<<(NSEG + 255) / 256, 256>>>(cnt);
    probe_kernel<<<16, 256>>>((const long long*)eidx);
    fill_kernel<<<(NE + 255) / 256, 256>>>(eidx, etype, ew, cnt, list);

    // 1) gather (slot #4: profiled) + weight rounding + overflow fallback
    gather_kernel<<<(NSEG * 8 + 255) / 256, 256>>>(x, cnt, list, upd);
    round_weights_kernel<<<WTOTAL / 256, 256>>>(mlpW, wih, whh);
    fallback_kernel<<<(NE + 255) / 256, 256>>>(x, ew, upd);

    // 2) hidden = relu(update @ mlpW^T + mlpb)  — A already tf32 (CVT_A=0)
    gemm_tf32<KU, 1, 0, 1><<<dim3(MB128, DH / 64), 256>>>(
        upd, wbuf + WOFF_MLP, mlpb, hid, NN, DH);

    // 3) gi = hidden @ w_ih^T + b_ih            — A already tf32 (CVT_A=0)
    gemm_tf32<DH, 0, 0, 0><<<dim3(MB128, G3 / 64), 256>>>(
        hid, wbuf + WOFF_IH, bih, gi, NN, G3);

    // 4) gh = x @ w_hh^T + b_hh                 — A raw fp32 (CVT_A=1)
    gemm_tf32<DI, 0, 1, 0><<<dim3(MB128, G3 / 64), 256>>>(
        x, wbuf + WOFF_HH, bhh, gh, NN, G3);

    // 5) GRU gates -> out (vectorized)
    gates_kernel<<<(NN * 16 + 255) / 256, 256>>>(x, gi, gh, out);
}

// round 15
// speedup vs baseline: 1.4192x; 1.0141x over previous
#include <cuda_runtime.h>
#include <cuda_bf16.h>
#include <math.h>
#include <stdint.h>

// Problem constants (shapes fixed by the dataset)
#define NN 100000           // nodes
#define NE 1000000          // edges
#define ET 4                // edge types
#define DI 64               // input dim
#define DH 256              // hidden dim
#define KU (ET*DI)          // 256 = update row width
#define G3 (3*DI)           // 192 = gate width
#define NSEG (NN*ET)        // 400000 segments
#define CAP 16              // edges per segment capacity (one 128B line; overflow handled)

// Scratch (device globals — allocation-free)
__device__ float g_update[(size_t)NN * KU];   // 102.4 MB
__device__ float g_hidden[(size_t)NN * DH];   // 102.4 MB
__device__ float g_gi[(size_t)NN * G3];       // 76.8 MB (edge lists pre-GEMM2: 400k*16*8B = 51.2MB)
__device__ float g_gh[(size_t)NN * G3];       // 76.8 MB (first 1.6MB = counts)
__device__ int   g_src[NE];                   // overflow-only
__device__ int   g_dst[NE];                   // overflow-only
__device__ int   g_typ[NE];                   // overflow-only
__device__ int   g_pos[NE];                   // overflow-only (read iff g_ovf)
__device__ int   g_is_i32;                    // 1 => edge arrays are int32
__device__ int   g_ovf;                       // 1 => at least one overflow edge

// Pre-rounded (tf32) weight copies
#define WOFF_MLP 0
#define WOFF_IH  (DH*KU)                   // 65536
#define WOFF_HH  (WOFF_IH + G3*DH)         // 114688
#define WTOTAL   (WOFF_HH + G3*DI)         // 126976
__device__ float g_wbuf[WTOTAL];

// ---------------------------------------------------------------------------
// tf32 helpers
// ---------------------------------------------------------------------------
__device__ __forceinline__ uint32_t to_tf32(float v) {
    uint32_t u;
    asm("cvt.rna.tf32.f32 %0, %1;" : "=r"(u) : "f"(v));
    return u;
}

__device__ __forceinline__ uint32_t smem_u32(const void* p) {
    return (uint32_t)__cvta_generic_to_shared(p);
}

// ---------------------------------------------------------------------------
// init: zero the segment counters + reset flags
// ---------------------------------------------------------------------------
__global__ void init_kernel(int* __restrict__ cnt) {
    int i = blockIdx.x * blockDim.x + threadIdx.x;
    if (i < NSEG) cnt[i] = 0;
    if (i == 0) { g_is_i32 = 0; g_ovf = 0; }
}

__global__ void probe_kernel(const long long* __restrict__ eidx) {
    int i = blockIdx.x * blockDim.x + threadIdx.x;   // 4096 probes
    long long v = eidx[i];
    if (v < 0 || v >= (long long)NN) atomicExch(&g_is_i32, 1);
}

// ---------------------------------------------------------------------------
// Fused convert+fill: read raw edge arrays (either dtype), bucket into
// per-(dst,type) lists of packed (src, w) 8B entries. Overflow edges set
// g_ovf and record src/dst/typ/pos for the fallback.
// ---------------------------------------------------------------------------
__global__ void fill_kernel(const void* __restrict__ eidx,
                            const void* __restrict__ etype,
                            const float* __restrict__ ew,
                            int* __restrict__ cnt,
                            unsigned long long* __restrict__ list) {
    int e = blockIdx.x * blockDim.x + threadIdx.x;
    if (e >= NE) return;
    int src, dst, t;
    if (g_is_i32) {
        const int* p = (const int*)eidx;
        src = p[e];
        dst = p[NE + e];
        t   = ((const int*)etype)[e];
    } else {
        const long long* p = (const long long*)eidx;
        src = (int)p[e];
        dst = (int)p[NE + e];
        t   = (int)((const long long*)etype)[e];
    }
    if ((unsigned)dst >= NN || (unsigned)t >= ET || (unsigned)src >= NN) return;
    int slot = dst * ET + t;
    int pos = atomicAdd(&cnt[slot], 1);
    if (pos < CAP) {
        unsigned long long pk =
            (unsigned long long)(unsigned)src |
            ((unsigned long long)__float_as_uint(ew[e]) << 32);
        list[(size_t)slot * CAP + pos] = pk;
    } else {                          // overflow: record for fallback
        g_pos[e] = pos;
        g_src[e] = src;
        g_dst[e] = dst;
        g_typ[e] = t;
        atomicExch(&g_ovf, 1);
    }
}

__global__ void round_weights_kernel(const float* __restrict__ mlpW,
                                     const float* __restrict__ wih,
                                     const float* __restrict__ whh) {
    int i = blockIdx.x * blockDim.x + threadIdx.x;
    if (i >= WTOTAL) return;
    float v;
    if (i < WOFF_IH)       v = mlpW[i];
    else if (i < WOFF_HH)  v = wih[i - WOFF_IH];
    else                   v = whh[i - WOFF_HH];
    g_wbuf[i] = __uint_as_float(to_tf32(v));
}

// ---------------------------------------------------------------------------
// gather: 8 threads/segment, each owns 8 consecutive floats (2x float4).
// List entries are loaded ONCE per group (2 per thread, covering CAP=16) and
// broadcast via __shfl_sync(width=8) — removes the 8x redundant L1 loads and
// the per-iteration dependent list load. Exclusive ownership -> plain stores.
// Output rounded rna->tf32 so GEMM1 skips its A-side cvt.
// ---------------------------------------------------------------------------
__global__ void gather_kernel(const float* __restrict__ x,
                              const int* __restrict__ cnt,
                              const unsigned long long* __restrict__ list,
                              float* __restrict__ upd) {
    int i = blockIdx.x * blockDim.x + threadIdx.x;   // NSEG*8 work items
    int seg = i >> 3;
    int t8  = i & 7;
    int c   = t8 * 8;          // float offset within the 64-wide row
    if (seg >= NSEG) return;
    int n = cnt[seg];
    if (n > CAP) n = CAP;
    const unsigned long long* lp = list + (size_t)seg * CAP;
    // group-cooperative list fetch (entries >= n are garbage, never used)
    unsigned long long e0 = lp[t8];
    unsigned long long e1 = lp[t8 + 8];
    float4 a0 = make_float4(0.f, 0.f, 0.f, 0.f);
    float4 a1 = make_float4(0.f, 0.f, 0.f, 0.f);
    for (int j = 0; j < n; j++) {
        unsigned long long pk = (j < 8)
            ? __shfl_sync(0xffffffffu, e0, j, 8)
            : __shfl_sync(0xffffffffu, e1, j - 8, 8);
        int   src = (int)(unsigned)(pk & 0xffffffffull);
        float w   = __uint_as_float((uint32_t)(pk >> 32));
        if ((unsigned)src < NN) {
            const float* xr = x + (size_t)src * DI + c;
            float4 v0 = *(const float4*)(xr);
            float4 v1 = *(const float4*)(xr + 4);
            a0.x += w * v0.x; a0.y += w * v0.y; a0.z += w * v0.z; a0.w += w * v0.w;
            a1.x += w * v1.x; a1.y += w * v1.y; a1.z += w * v1.z; a1.w += w * v1.w;
        }
    }
    a0.x = __uint_as_float(to_tf32(a0.x));
    a0.y = __uint_as_float(to_tf32(a0.y));
    a0.z = __uint_as_float(to_tf32(a0.z));
    a0.w = __uint_as_float(to_tf32(a0.w));
    a1.x = __uint_as_float(to_tf32(a1.x));
    a1.y = __uint_as_float(to_tf32(a1.y));
    a1.z = __uint_as_float(to_tf32(a1.z));
    a1.w = __uint_as_float(to_tf32(a1.w));
    float* ur = upd + (size_t)seg * DI + c;
    *(float4*)(ur)     = a0;
    *(float4*)(ur + 4) = a1;
}

// Overflow edges (essentially never) — whole grid exits on one flag load
// unless fill detected an overflow; then per-edge RED with tf32 addends.
__global__ void fallback_kernel(const float* __restrict__ x,
                                const float* __restrict__ ew,
                                float* __restrict__ upd) {
    if (!g_ovf) return;
    int e = blockIdx.x * blockDim.x + threadIdx.x;
    if (e >= NE) return;
    if (g_pos[e] < CAP) return;
    int src = g_src[e];
    int dst = g_dst[e];
    int t   = g_typ[e];
    if ((unsigned)src >= NN || (unsigned)dst >= NN || (unsigned)t >= ET) return;
    float w = ew[e];
    float* drow = upd + ((size_t)dst * ET + t) * DI;
    for (int c = 0; c < 16; c++) {
        float4 v = *(const float4*)(x + (size_t)src * DI + c * 4);
        float p0 = __uint_as_float(to_tf32(w * v.x));
        float p1 = __uint_as_float(to_tf32(w * v.y));
        float p2 = __uint_as_float(to_tf32(w * v.z));
        float p3 = __uint_as_float(to_tf32(w * v.w));
        asm volatile("red.global.add.v4.f32 [%0], {%1,%2,%3,%4};"
                     :: "l"(drow + c * 4), "f"(p0), "f"(p1), "f"(p2), "f"(p3)
                     : "memory");
    }
}

// ---------------------------------------------------------------------------
// TF32 mma.sync GEMM, BK=32, 3-stage cp.async (known good)
// ---------------------------------------------------------------------------
#define MMA_TF32(d, a, b0, b1)                                                 \
    asm volatile(                                                              \
        "mma.sync.aligned.m16n8k8.row.col.f32.tf32.tf32.f32 "                  \
        "{%0,%1,%2,%3},{%4,%5,%6,%7},{%8,%9},{%0,%1,%2,%3};"                   \
        : "+f"((d)[0]), "+f"((d)[1]), "+f"((d)[2]), "+f"((d)[3])               \
        : "r"((a)[0]), "r"((a)[1]), "r"((a)[2]), "r"((a)[3]),                  \
          "r"(b0), "r"(b1))

template<int K, int RELU, int CVT_A, int CVT_OUT>
__global__ void __launch_bounds__(256) gemm_tf32(const float* __restrict__ A,
                                                 const float* __restrict__ B,
                                                 const float* __restrict__ bias,
                                                 float* __restrict__ C,
                                                 int M, int N) {
    __shared__ float As[3][128][36];
    __shared__ float Bs[3][64][36];

    const int tid  = threadIdx.x;
    const int lane = tid & 31;
    const int w    = tid >> 5;
    const int wm   = (w & 3) * 32;
    const int wn   = (w >> 2) * 32;
    const int m0   = blockIdx.x * 128;
    const int n0   = blockIdx.y * 64;

    const int lrow = tid >> 3;
    const int lcol = (tid & 7) * 4;

    const int niter = K / 32;

    auto issue_tile = [&](int it, int s) {
        int k0 = it * 32;
#pragma unroll
        for (int p = 0; p < 4; p++) {
            int r  = p * 32 + lrow;
            int gm = m0 + r;
            const float* src = A + (size_t)gm * K + k0 + lcol;
            uint32_t dst = smem_u32(&As[s][r][lcol]);
            int sz = (gm < M) ? 16 : 0;
            asm volatile("cp.async.cg.shared.global [%0], [%1], 16, %2;"
                         :: "r"(dst), "l"(src), "r"(sz));
        }
#pragma unroll
        for (int p = 0; p < 2; p++) {
            int r = p * 32 + lrow;
            const float* src = B + (size_t)(n0 + r) * K + k0 + lcol;
            uint32_t dst = smem_u32(&Bs[s][r][lcol]);
            asm volatile("cp.async.cg.shared.global [%0], [%1], 16;"
                         :: "r"(dst), "l"(src));
        }
    };

    float acc[2][4][4];
#pragma unroll
    for (int mt = 0; mt < 2; mt++)
#pragma unroll
        for (int nt = 0; nt < 4; nt++)
#pragma unroll
            for (int j = 0; j < 4; j++) acc[mt][nt][j] = 0.f;

    issue_tile(0, 0);
    asm volatile("cp.async.commit_group;");
    if (niter > 1) issue_tile(1, 1);
    asm volatile("cp.async.commit_group;");

    int s = 0, s2 = 2;
    for (int i = 0; i < niter; i++) {
        asm volatile("cp.async.wait_group 1;");
        __syncthreads();

        if (i + 2 < niter) issue_tile(i + 2, s2);
        asm volatile("cp.async.commit_group;");

#pragma unroll
        for (int ks = 0; ks < 32; ks += 8) {
            uint32_t af[2][4];
#pragma unroll
            for (int mt = 0; mt < 2; mt++) {
                int r = wm + mt * 16 + (lane >> 2);
                int c = ks + (lane & 3);
                if (CVT_A) {
                    af[mt][0] = to_tf32(As[s][r][c]);
                    af[mt][1] = to_tf32(As[s][r + 8][c]);
                    af[mt][2] = to_tf32(As[s][r][c + 4]);
                    af[mt][3] = to_tf32(As[s][r + 8][c + 4]);
                } else {
                    af[mt][0] = __float_as_uint(As[s][r][c]);
                    af[mt][1] = __float_as_uint(As[s][r + 8][c]);
                    af[mt][2] = __float_as_uint(As[s][r][c + 4]);
                    af[mt][3] = __float_as_uint(As[s][r + 8][c + 4]);
                }
            }
#pragma unroll
            for (int nt = 0; nt < 4; nt++) {
                int cn = wn + nt * 8 + (lane >> 2);
                int ck = ks + (lane & 3);
                uint32_t b0 = __float_as_uint(Bs[s][cn][ck]);
                uint32_t b1 = __float_as_uint(Bs[s][cn][ck + 4]);
                MMA_TF32(acc[0][nt], af[0], b0, b1);
                MMA_TF32(acc[1][nt], af[1], b0, b1);
            }
        }
        s  = (s  == 2) ? 0 : s  + 1;
        s2 = (s2 == 2) ? 0 : s2 + 1;
    }

#pragma unroll
    for (int mt = 0; mt < 2; mt++) {
#pragma unroll
        for (int nt = 0; nt < 4; nt++) {
            int row = m0 + wm + mt * 16 + (lane >> 2);
            int col = n0 + wn + nt * 8 + 2 * (lane & 3);
            float b0v = bias[col];
            float b1v = bias[col + 1];
            float v0 = acc[mt][nt][0] + b0v;
            float v1 = acc[mt][nt][1] + b1v;
            float v2 = acc[mt][nt][2] + b0v;
            float v3 = acc[mt][nt][3] + b1v;
            if (RELU) {
                v0 = fmaxf(v0, 0.f); v1 = fmaxf(v1, 0.f);
                v2 = fmaxf(v2, 0.f); v3 = fmaxf(v3, 0.f);
            }
            if (CVT_OUT) {
                v0 = __uint_as_float(to_tf32(v0));
                v1 = __uint_as_float(to_tf32(v1));
                v2 = __uint_as_float(to_tf32(v2));
                v3 = __uint_as_float(to_tf32(v3));
            }
            if (row < M)
                *(float2*)(C + (size_t)row * N + col) = make_float2(v0, v1);
            if (row + 8 < M)
                *(float2*)(C + (size_t)(row + 8) * N + col) = make_float2(v2, v3);
        }
    }
}

// ---------------------------------------------------------------------------
// GRU gate epilogue, vectorized (known good)
// ---------------------------------------------------------------------------
__global__ void gates_kernel(const float* __restrict__ x,
                             const float* __restrict__ gi,
                             const float* __restrict__ gh,
                             float* __restrict__ out) {
    int i = blockIdx.x * blockDim.x + threadIdx.x;   // NN*16 work items
    if (i >= NN * 16) return;
    int m = i >> 4;
    int c = (i & 15) * 4;
    const float* gim = gi + (size_t)m * G3;
    const float* ghm = gh + (size_t)m * G3;
    float4 ir  = *(const float4*)(gim + c);
    float4 iz  = *(const float4*)(gim + 64 + c);
    float4 in_ = *(const float4*)(gim + 128 + c);
    float4 hr  = *(const float4*)(ghm + c);
    float4 hz  = *(const float4*)(ghm + 64 + c);
    float4 hn  = *(const float4*)(ghm + 128 + c);
    float4 hv  = *(const float4*)(x + (size_t)m * DI + c);
    float4 o;
    {
        float r = 1.f / (1.f + expf(-(ir.x + hr.x)));
        float z = 1.f / (1.f + expf(-(iz.x + hz.x)));
        float n = tanhf(in_.x + r * hn.x);
        o.x = (1.f - z) * n + z * hv.x;
    }
    {
        float r = 1.f / (1.f + expf(-(ir.y + hr.y)));
        float z = 1.f / (1.f + expf(-(iz.y + hz.y)));
        float n = tanhf(in_.y + r * hn.y);
        o.y = (1.f - z) * n + z * hv.y;
    }
    {
        float r = 1.f / (1.f + expf(-(ir.z + hr.z)));
        float z = 1.f / (1.f + expf(-(iz.z + hz.z)));
        float n = tanhf(in_.z + r * hn.z);
        o.z = (1.f - z) * n + z * hv.z;
    }
    {
        float r = 1.f / (1.f + expf(-(ir.w + hr.w)));
        float z = 1.f / (1.f + expf(-(iz.w + hz.w)));
        float n = tanhf(in_.w + r * hn.w);
        o.w = (1.f - z) * n + z * hv.w;
    }
    *(float4*)(out + (size_t)m * DI + c) = o;
}

// ---------------------------------------------------------------------------
// Launch
// ---------------------------------------------------------------------------
extern "C" void kernel_launch(void* const* d_in, const int* in_sizes, int n_in,
                              void* d_out, int out_size) {
    const float* x     = (const float*)d_in[0];      // [NN, 64]
    const void*  eidx  = d_in[1];                    // [2, NE] int32 or int64
    const void*  etype = d_in[2];                    // [NE]
    const float* ew    = (const float*)d_in[3];      // [NE]
    const float* mlpW  = (const float*)d_in[4];      // [256, 256]
    const float* mlpb  = (const float*)d_in[5];      // [256]
    const float* wih   = (const float*)d_in[6];      // [192, 256]
    const float* whh   = (const float*)d_in[7];      // [192, 64]
    const float* bih   = (const float*)d_in[8];      // [192]
    const float* bhh   = (const float*)d_in[9];      // [192]
    float*       out   = (float*)d_out;              // [NN, 64]

    float *upd, *hid, *gi, *gh, *wbuf;
    cudaGetSymbolAddress((void**)&upd, g_update);
    cudaGetSymbolAddress((void**)&hid, g_hidden);
    cudaGetSymbolAddress((void**)&gi,  g_gi);
    cudaGetSymbolAddress((void**)&gh,  g_gh);
    cudaGetSymbolAddress((void**)&wbuf, g_wbuf);

    int* cnt = (int*)gh;                                // 1.6MB of g_gh
    unsigned long long* list = (unsigned long long*)gi; // 51.2MB of g_gi

    const int MB128 = (NN + 127) / 128;   // 782

    // 0) init counters+flags, dtype probe, fused bucket-fill
    init_kernel<<<(NSEG + 255) / 256, 256>>>(cnt);
    probe_kernel<<<16, 256>>>((const long long*)eidx);
    fill_kernel<<<(NE + 255) / 256, 256>>>(eidx, etype, ew, cnt, list);

    // 1) gather (slot #4: profiled) + weight rounding + overflow fallback
    gather_kernel<<<(NSEG * 8 + 255) / 256, 256>>>(x, cnt, list, upd);
    round_weights_kernel<<<WTOTAL / 256, 256>>>(mlpW, wih, whh);
    fallback_kernel<<<(NE + 255) / 256, 256>>>(x, ew, upd);

    // 2) hidden = relu(update @ mlpW^T + mlpb)  — A already tf32 (CVT_A=0)
    gemm_tf32<KU, 1, 0, 1><<<dim3(MB128, DH / 64), 256>>>(
        upd, wbuf + WOFF_MLP, mlpb, hid, NN, DH);

    // 3) gi = hidden @ w_ih^T + b_ih            — A already tf32 (CVT_A=0)
    gemm_tf32<DH, 0, 0, 0><<<dim3(MB128, G3 / 64), 256>>>(
        hid, wbuf + WOFF_IH, bih, gi, NN, G3);

    // 4) gh = x @ w_hh^T + b_hh                 — A raw fp32 (CVT_A=1)
    gemm_tf32<DI, 0, 1, 0><<<dim3(MB128, G3 / 64), 256>>>(
        x, wbuf + WOFF_HH, bhh, gh, NN, G3);

    // 5) GRU gates -> out (vectorized)
    gates_kernel<<<(NN * 16 + 255) / 256, 256>>>(x, gi, gh, out);
}